// round 5
// baseline (speedup 1.0000x reference)
#include <cuda_runtime.h>
#include <cuda_bf16.h>
#include <math.h>
#include <stdint.h>

// Problem constants
#define Bc  2
#define Sc  2048
#define Dc  1024
#define Hc  16
#define HDc 64
#define BSc (Bc * Sc)

// Scratch (device globals; allocation inside kernel_launch is forbidden)
__device__ float g_q[(size_t)Bc * Sc * Dc];
__device__ float g_k[(size_t)Bc * Sc * Dc];
__device__ float g_v[(size_t)Bc * Sc * Dc];
__device__ float g_ctx[(size_t)Bc * Sc * Dc];
__device__ float g_attn_scratch[(size_t)Bc * Hc * Sc * Sc];

// ---------------------------------------------------------------------------
// bf16 split helpers: x = hi + lo, hi = bf16(x), lo = bf16(x - hi).
// Words are bf16x2 packed (low half = first/even-k element).
// ---------------------------------------------------------------------------
__device__ __forceinline__ void split2(float x, float y, uint32_t& hi, uint32_t& lo) {
    __nv_bfloat162 h = __floats2bfloat162_rn(x, y);
    float rx = x - __bfloat162float(h.x);
    float ry = y - __bfloat162float(h.y);
    __nv_bfloat162 l = __floats2bfloat162_rn(rx, ry);
    hi = *reinterpret_cast<uint32_t*>(&h);
    lo = *reinterpret_cast<uint32_t*>(&l);
}

// m16n8k16 row.col bf16 MMA, fp32 accumulate (standard sm_80+ fragment map)
__device__ __forceinline__ void mma16(float c[4], const uint32_t a[4], const uint32_t b[2]) {
    asm volatile(
        "mma.sync.aligned.m16n8k16.row.col.f32.bf16.bf16.f32 "
        "{%0,%1,%2,%3}, {%4,%5,%6,%7}, {%8,%9}, {%0,%1,%2,%3};"
        : "+f"(c[0]), "+f"(c[1]), "+f"(c[2]), "+f"(c[3])
        : "r"(a[0]), "r"(a[1]), "r"(a[2]), "r"(a[3]), "r"(b[0]), "r"(b[1]));
}

// ---------------------------------------------------------------------------
// bf16x3 tensor-core GEMM + bias: C[M,N] = A[M,K] @ W[K,N] + b[N]
// CTA tile 128x128, BK=32, 256 threads (8 warps 2x4), warp tile 64x32.
// A staged [m][k-pair-word] str 20; W staged transposed [n][k-pair-word] str 20.
// ---------------------------------------------------------------------------
#define GSTR 20

__global__ __launch_bounds__(256) void gemm_bias_tc(const float* __restrict__ A,
                                                    const float* __restrict__ W,
                                                    const float* __restrict__ bias,
                                                    float* __restrict__ C,
                                                    int M, int N, int K) {
    __shared__ uint32_t Ah[128 * GSTR], Al[128 * GSTR];
    __shared__ uint32_t Bh[128 * GSTR], Bl[128 * GSTR];

    const int tid = threadIdx.x;
    const int w = tid >> 5, lane = tid & 31;
    const int g = lane >> 2, t = lane & 3;
    const int m0 = blockIdx.x * 128, n0 = blockIdx.y * 128;
    const int wm = (w & 1) * 64;
    const int wn = (w >> 1) * 32;

    float acc[4][4][4] = {};

    for (int k0 = 0; k0 < K; k0 += 32) {
        // Stage A 128x32: k-pairs packed along the row
#pragma unroll
        for (int i = 0; i < 4; i++) {
            int idx = tid + i * 256;
            int r = idx >> 3, c4 = idx & 7;
            float4 v = *(const float4*)&A[(size_t)(m0 + r) * K + k0 + c4 * 4];
            uint32_t h0, l0, h1, l1;
            split2(v.x, v.y, h0, l0);
            split2(v.z, v.w, h1, l1);
            Ah[r * GSTR + c4 * 2] = h0; Ah[r * GSTR + c4 * 2 + 1] = h1;
            Al[r * GSTR + c4 * 2] = l0; Al[r * GSTR + c4 * 2 + 1] = l1;
        }
        // Stage W 32x128 transposed: word j of row n = (W[k0+2j][n], W[k0+2j+1][n])
#pragma unroll
        for (int i = 0; i < 2; i++) {
            int id = tid + i * 256;
            int j = id >> 5, ng = id & 31;
            float4 v0 = *(const float4*)&W[(size_t)(k0 + 2 * j) * N + n0 + ng * 4];
            float4 v1 = *(const float4*)&W[(size_t)(k0 + 2 * j + 1) * N + n0 + ng * 4];
            float a0[4] = {v0.x, v0.y, v0.z, v0.w};
            float a1[4] = {v1.x, v1.y, v1.z, v1.w};
#pragma unroll
            for (int e = 0; e < 4; e++) {
                uint32_t hh, ll;
                split2(a0[e], a1[e], hh, ll);
                Bh[(ng * 4 + e) * GSTR + j] = hh;
                Bl[(ng * 4 + e) * GSTR + j] = ll;
            }
        }
        __syncthreads();

#pragma unroll
        for (int ks = 0; ks < 2; ks++) {
            uint32_t ah[4][4], al[4][4], bh[4][2], bl[4][2];
#pragma unroll
            for (int mf = 0; mf < 4; mf++) {
                int r = wm + mf * 16 + g;
                ah[mf][0] = Ah[r * GSTR + ks * 8 + t];
                ah[mf][1] = Ah[(r + 8) * GSTR + ks * 8 + t];
                ah[mf][2] = Ah[r * GSTR + ks * 8 + t + 4];
                ah[mf][3] = Ah[(r + 8) * GSTR + ks * 8 + t + 4];
                al[mf][0] = Al[r * GSTR + ks * 8 + t];
                al[mf][1] = Al[(r + 8) * GSTR + ks * 8 + t];
                al[mf][2] = Al[r * GSTR + ks * 8 + t + 4];
                al[mf][3] = Al[(r + 8) * GSTR + ks * 8 + t + 4];
            }
#pragma unroll
            for (int nf = 0; nf < 4; nf++) {
                int rr = wn + nf * 8 + g;
                bh[nf][0] = Bh[rr * GSTR + ks * 8 + t];
                bh[nf][1] = Bh[rr * GSTR + ks * 8 + t + 4];
                bl[nf][0] = Bl[rr * GSTR + ks * 8 + t];
                bl[nf][1] = Bl[rr * GSTR + ks * 8 + t + 4];
            }
#pragma unroll
            for (int mf = 0; mf < 4; mf++)
#pragma unroll
                for (int nf = 0; nf < 4; nf++) {
                    mma16(acc[mf][nf], ah[mf], bh[nf]);
                    mma16(acc[mf][nf], ah[mf], bl[nf]);
                    mma16(acc[mf][nf], al[mf], bh[nf]);
                }
        }
        __syncthreads();
    }

    // Epilogue: bias + store (C frag: rows g/g+8, cols 2t/2t+1)
#pragma unroll
    for (int mf = 0; mf < 4; mf++) {
#pragma unroll
        for (int nf = 0; nf < 4; nf++) {
            int col = n0 + wn + nf * 8 + 2 * t;
            float b0v = bias[col], b1v = bias[col + 1];
            int row = m0 + wm + mf * 16 + g;
            float2 v0 = {acc[mf][nf][0] + b0v, acc[mf][nf][1] + b1v};
            *(float2*)&C[(size_t)row * N + col] = v0;
            float2 v1 = {acc[mf][nf][2] + b0v, acc[mf][nf][3] + b1v};
            *(float2*)&C[(size_t)(row + 8) * N + col] = v1;
        }
    }
}

// ---------------------------------------------------------------------------
// Attention: per (b, h, 64-query tile), bf16x3 tensor cores.
// Pass 1: scores per 128-key slab -> raw to attn + online m,l
// Pass 2: re-read raw, normalize (write probs), P@V split-K across warp pairs.
// Smem (32-bit words):
//   Qh[64*36] Ql[64*36] | Kh[128*36] Kl[128*36] (reused as V [64*69]) |
//   S region 8704 words (pass1: fp32 scores 64x132; pass2: Ph/Pl 64x68 each)
// ---------------------------------------------------------------------------
#define QH_OFF 0
#define QL_OFF 2304
#define KH_OFF 4608
#define KL_OFF 9216
#define SS_OFF 13824
#define ATTN_WORDS 22528
#define ATTN_SMEM_BYTES (ATTN_WORDS * 4)
#define VSTR 69

__global__ __launch_bounds__(256) void attn_tc(float* __restrict__ attn) {
    extern __shared__ uint32_t sh[];
    uint32_t* Qh = sh + QH_OFF;
    uint32_t* Ql = sh + QL_OFF;
    uint32_t* Kh = sh + KH_OFF;     // pass2: Vh [d][key-word] stride 69
    uint32_t* Kl = sh + KL_OFF;     // pass2: Vl
    uint32_t* Ssh = sh + SS_OFF;          // pass2: P hi [q][key-word] stride 68
    uint32_t* Ssl = sh + SS_OFF + 4352;   // pass2: P lo
    float*    Ssf = (float*)(sh + SS_OFF); // pass1: fp32 scores [q][k] stride 132

    const int tid = threadIdx.x;
    const int w = tid >> 5, lane = tid & 31;
    const int g = lane >> 2, t = lane & 3;
    const int b = blockIdx.z, h = blockIdx.y, q0 = blockIdx.x << 6;
    const int qr = tid >> 2, qg = tid & 3;
    const float scale = 0.125f;

    float* attn_base = attn + (((size_t)b * Hc + h) * Sc + q0) * Sc;

    // Stage Q tile 64x64 (split), [q][k-pair-word] stride 36
#pragma unroll
    for (int i = 0; i < 4; i++) {
        int idx = tid + i * 256;
        int r = idx >> 4, c4 = idx & 15;
        float4 v = *(const float4*)&g_q[((size_t)b * Sc + q0 + r) * Dc + h * HDc + c4 * 4];
        uint32_t h0, l0, h1, l1;
        split2(v.x, v.y, h0, l0);
        split2(v.z, v.w, h1, l1);
        Qh[r * 36 + c4 * 2] = h0; Qh[r * 36 + c4 * 2 + 1] = h1;
        Ql[r * 36 + c4 * 2] = l0; Ql[r * 36 + c4 * 2 + 1] = l1;
    }

    float m = -INFINITY, l = 0.0f;

    // Pass-1 warp map: 2x4 grid of 32x32 score tiles over 64q x 128k
    const int wm1 = (w & 1) * 32;
    const int wn1 = (w >> 1) * 32;

    for (int kk = 0; kk < Sc; kk += 128) {
        // Stage K slab 128x64 (split), [key][d-pair-word] stride 36
#pragma unroll
        for (int i = 0; i < 8; i++) {
            int idx = tid + i * 256;
            int r = idx >> 4, c4 = idx & 15;
            float4 v = *(const float4*)&g_k[((size_t)b * Sc + kk + r) * Dc + h * HDc + c4 * 4];
            uint32_t h0, l0, h1, l1;
            split2(v.x, v.y, h0, l0);
            split2(v.z, v.w, h1, l1);
            Kh[r * 36 + c4 * 2] = h0; Kh[r * 36 + c4 * 2 + 1] = h1;
            Kl[r * 36 + c4 * 2] = l0; Kl[r * 36 + c4 * 2 + 1] = l1;
        }
        __syncthreads();

        float c[2][4][4] = {};
#pragma unroll
        for (int ks = 0; ks < 4; ks++) {
            uint32_t ah[2][4], al[2][4], bh[4][2], bl[4][2];
#pragma unroll
            for (int mf = 0; mf < 2; mf++) {
                int r = wm1 + mf * 16 + g;
                ah[mf][0] = Qh[r * 36 + ks * 8 + t];
                ah[mf][1] = Qh[(r + 8) * 36 + ks * 8 + t];
                ah[mf][2] = Qh[r * 36 + ks * 8 + t + 4];
                ah[mf][3] = Qh[(r + 8) * 36 + ks * 8 + t + 4];
                al[mf][0] = Ql[r * 36 + ks * 8 + t];
                al[mf][1] = Ql[(r + 8) * 36 + ks * 8 + t];
                al[mf][2] = Ql[r * 36 + ks * 8 + t + 4];
                al[mf][3] = Ql[(r + 8) * 36 + ks * 8 + t + 4];
            }
#pragma unroll
            for (int nf = 0; nf < 4; nf++) {
                int kr = wn1 + nf * 8 + g;
                bh[nf][0] = Kh[kr * 36 + ks * 8 + t];
                bh[nf][1] = Kh[kr * 36 + ks * 8 + t + 4];
                bl[nf][0] = Kl[kr * 36 + ks * 8 + t];
                bl[nf][1] = Kl[kr * 36 + ks * 8 + t + 4];
            }
#pragma unroll
            for (int mf = 0; mf < 2; mf++)
#pragma unroll
                for (int nf = 0; nf < 4; nf++) {
                    mma16(c[mf][nf], ah[mf], bh[nf]);
                    mma16(c[mf][nf], ah[mf], bl[nf]);
                    mma16(c[mf][nf], al[mf], bh[nf]);
                }
        }
        // Scaled scores -> smem (fp32, stride 132)
#pragma unroll
        for (int mf = 0; mf < 2; mf++)
#pragma unroll
            for (int nf = 0; nf < 4; nf++) {
                int row = wm1 + mf * 16 + g, col = wn1 + nf * 8 + 2 * t;
                float2 v0 = {c[mf][nf][0] * scale, c[mf][nf][1] * scale};
                *(float2*)&Ssf[row * 132 + col] = v0;
                float2 v1 = {c[mf][nf][2] * scale, c[mf][nf][3] * scale};
                *(float2*)&Ssf[(row + 8) * 132 + col] = v1;
            }
        __syncthreads();

        // Stats + coalesced raw-score write (thread: row qr, 32 elems)
        float tmax = -INFINITY;
#pragma unroll
        for (int j = 0; j < 8; j++) {
            float4 v = *(const float4*)&Ssf[qr * 132 + qg * 32 + j * 4];
            *(float4*)&attn_base[(size_t)qr * Sc + kk + qg * 32 + j * 4] = v;
            tmax = fmaxf(tmax, fmaxf(fmaxf(v.x, v.y), fmaxf(v.z, v.w)));
        }
        tmax = fmaxf(tmax, __shfl_xor_sync(0xffffffffu, tmax, 1));
        tmax = fmaxf(tmax, __shfl_xor_sync(0xffffffffu, tmax, 2));
        const float m_new = fmaxf(m, tmax);
        float ls = 0.0f;
#pragma unroll
        for (int j = 0; j < 8; j++) {
            float4 v = *(const float4*)&Ssf[qr * 132 + qg * 32 + j * 4];
            ls += __expf(v.x - m_new) + __expf(v.y - m_new) +
                  __expf(v.z - m_new) + __expf(v.w - m_new);
        }
        ls += __shfl_xor_sync(0xffffffffu, ls, 1);
        ls += __shfl_xor_sync(0xffffffffu, ls, 2);
        l = l * __expf(m - m_new) + ls;
        m = m_new;
        // next iteration's post-load sync orders Ssf reuse
    }
    __syncthreads();  // separate pass-1 reads from pass-2 writes

    const float inv_l = 1.0f / l;

    // Pass-2 warp map: (q half, d half, k half); split-K across warp pairs
    const int pm = (w & 1) * 32;
    const int pn = ((w >> 1) & 1) * 32;
    const int pkw = (w >> 2) * 32;   // k-half in pair-words (64 keys = 32 words)

    float acc[2][4][4] = {};
    for (int kk = 0; kk < Sc; kk += 128) {
        // Stage V slab transposed: Vh[d][key-word] stride 69 (keys pair-packed)
#pragma unroll
        for (int i = 0; i < 4; i++) {
            int id = tid + i * 256;
            int j = id >> 4, dg = id & 15;
            const float* r0 = &g_v[((size_t)b * Sc + kk + 2 * j) * Dc + h * HDc + dg * 4];
            float4 v0 = *(const float4*)r0;
            float4 v1 = *(const float4*)(r0 + Dc);
            float a0[4] = {v0.x, v0.y, v0.z, v0.w};
            float a1[4] = {v1.x, v1.y, v1.z, v1.w};
#pragma unroll
            for (int e = 0; e < 4; e++) {
                uint32_t hh, ll;
                split2(a0[e], a1[e], hh, ll);
                Kh[(dg * 4 + e) * VSTR + j] = hh;
                Kl[(dg * 4 + e) * VSTR + j] = ll;
            }
        }
        // Read raw scores, normalize, write probs to global, split P into smem
#pragma unroll
        for (int j = 0; j < 8; j++) {
            size_t ga = (size_t)qr * Sc + kk + qg * 32 + j * 4;
            float4 s4 = *(const float4*)&attn_base[ga];
            float4 p4;
            p4.x = __expf(s4.x - m) * inv_l;
            p4.y = __expf(s4.y - m) * inv_l;
            p4.z = __expf(s4.z - m) * inv_l;
            p4.w = __expf(s4.w - m) * inv_l;
            *(float4*)&attn_base[ga] = p4;
            uint32_t h0, l0, h1, l1;
            split2(p4.x, p4.y, h0, l0);
            split2(p4.z, p4.w, h1, l1);
            int wo = qr * 68 + qg * 16 + j * 2;
            Ssh[wo] = h0; Ssh[wo + 1] = h1;
            Ssl[wo] = l0; Ssl[wo + 1] = l1;
        }
        __syncthreads();

#pragma unroll
        for (int ks = 0; ks < 4; ks++) {
            uint32_t ah[2][4], al[2][4], bh[4][2], bl[4][2];
#pragma unroll
            for (int mf = 0; mf < 2; mf++) {
                int r = pm + mf * 16 + g;
                ah[mf][0] = Ssh[r * 68 + pkw + ks * 8 + t];
                ah[mf][1] = Ssh[(r + 8) * 68 + pkw + ks * 8 + t];
                ah[mf][2] = Ssh[r * 68 + pkw + ks * 8 + t + 4];
                ah[mf][3] = Ssh[(r + 8) * 68 + pkw + ks * 8 + t + 4];
                al[mf][0] = Ssl[r * 68 + pkw + ks * 8 + t];
                al[mf][1] = Ssl[(r + 8) * 68 + pkw + ks * 8 + t];
                al[mf][2] = Ssl[r * 68 + pkw + ks * 8 + t + 4];
                al[mf][3] = Ssl[(r + 8) * 68 + pkw + ks * 8 + t + 4];
            }
#pragma unroll
            for (int nf = 0; nf < 4; nf++) {
                int rr = pn + nf * 8 + g;
                bh[nf][0] = Kh[rr * VSTR + pkw + ks * 8 + t];
                bh[nf][1] = Kh[rr * VSTR + pkw + ks * 8 + t + 4];
                bl[nf][0] = Kl[rr * VSTR + pkw + ks * 8 + t];
                bl[nf][1] = Kl[rr * VSTR + pkw + ks * 8 + t + 4];
            }
#pragma unroll
            for (int mf = 0; mf < 2; mf++)
#pragma unroll
                for (int nf = 0; nf < 4; nf++) {
                    mma16(acc[mf][nf], ah[mf], bh[nf]);
                    mma16(acc[mf][nf], ah[mf], bl[nf]);
                    mma16(acc[mf][nf], al[mf], bh[nf]);
                }
        }
        __syncthreads();
    }

    // Split-K reduce: warps 4..7 stage partials into the S region (fp32)
    float* stage = (float*)Ssh;
    if (w >= 4) {
#pragma unroll
        for (int mf = 0; mf < 2; mf++)
#pragma unroll
            for (int nf = 0; nf < 4; nf++) {
                int row = pm + mf * 16 + g, col = pn + nf * 8 + 2 * t;
                *(float2*)&stage[row * 68 + col] =
                    make_float2(acc[mf][nf][0], acc[mf][nf][1]);
                *(float2*)&stage[(row + 8) * 68 + col] =
                    make_float2(acc[mf][nf][2], acc[mf][nf][3]);
            }
    }
    __syncthreads();
    if (w < 4) {
#pragma unroll
        for (int mf = 0; mf < 2; mf++)
#pragma unroll
            for (int nf = 0; nf < 4; nf++) {
                int row = pm + mf * 16 + g, col = pn + nf * 8 + 2 * t;
                float2 o0 = *(const float2*)&stage[row * 68 + col];
                float2 o1 = *(const float2*)&stage[(row + 8) * 68 + col];
                o0.x += acc[mf][nf][0]; o0.y += acc[mf][nf][1];
                o1.x += acc[mf][nf][2]; o1.y += acc[mf][nf][3];
                *(float2*)&g_ctx[((size_t)b * Sc + q0 + row) * Dc + h * HDc + col] = o0;
                *(float2*)&g_ctx[((size_t)b * Sc + q0 + row + 8) * Dc + h * HDc + col] = o1;
            }
    }
}

// ---------------------------------------------------------------------------
extern "C" void kernel_launch(void* const* d_in, const int* in_sizes, int n_in,
                              void* d_out, int out_size) {
    const float* query = (const float*)d_in[0];
    const float* key_  = (const float*)d_in[1];
    const float* value = (const float*)d_in[2];
    const float* Wq = (const float*)d_in[3];
    const float* bq = (const float*)d_in[4];
    const float* Wk = (const float*)d_in[5];
    const float* bk = (const float*)d_in[6];
    const float* Wv = (const float*)d_in[7];
    const float* bv = (const float*)d_in[8];
    const float* Wo = (const float*)d_in[9];
    const float* bo = (const float*)d_in[10];
    float* out = (float*)d_out;

    float *dq, *dk, *dv, *dctx;
    cudaGetSymbolAddress((void**)&dq,  g_q);
    cudaGetSymbolAddress((void**)&dk,  g_k);
    cudaGetSymbolAddress((void**)&dv,  g_v);
    cudaGetSymbolAddress((void**)&dctx, g_ctx);

    const size_t OUT_ELEMS  = (size_t)Bc * Sc * Dc;
    const size_t ATTN_ELEMS = (size_t)Bc * Hc * Sc * Sc;
    float* attn_ptr;
    if ((size_t)out_size >= OUT_ELEMS + ATTN_ELEMS) {
        attn_ptr = out + OUT_ELEMS;
    } else {
        cudaGetSymbolAddress((void**)&attn_ptr, g_attn_scratch);
    }

    cudaFuncSetAttribute(attn_tc,
                         cudaFuncAttributeMaxDynamicSharedMemorySize,
                         ATTN_SMEM_BYTES);

    dim3 ggrid(BSc / 128, Dc / 128);  // 32 x 8

    gemm_bias_tc<<<ggrid, 256>>>(query, Wq, bq, dq, BSc, Dc, Dc);
    gemm_bias_tc<<<ggrid, 256>>>(key_,  Wk, bk, dk, BSc, Dc, Dc);
    gemm_bias_tc<<<ggrid, 256>>>(value, Wv, bv, dv, BSc, Dc, Dc);

    attn_tc<<<dim3(Sc / 64, Hc, Bc), 256, ATTN_SMEM_BYTES>>>(attn_ptr);

    gemm_bias_tc<<<ggrid, 256>>>(dctx, Wo, bo, out, BSc, Dc, Dc);
}

// round 6
// speedup vs baseline: 2.1616x; 2.1616x over previous
#include <cuda_runtime.h>
#include <math.h>
#include <stdint.h>

// Problem constants
#define Bc  2
#define Sc  2048
#define Dc  1024
#define Hc  16
#define HDc 64
#define BSc (Bc * Sc)
#define BHS (Bc * Hc * Sc)   // 65536 attention rows

// Scratch (device globals; allocation inside kernel_launch is forbidden)
__device__ float g_q[(size_t)Bc * Sc * Dc];
__device__ float g_k[(size_t)Bc * Sc * Dc];
__device__ float g_v[(size_t)Bc * Sc * Dc];
__device__ float g_ctx[(size_t)Bc * Sc * Dc];
__device__ float g_mbuf[BHS];
__device__ float g_lbuf[BHS];
__device__ float g_attn_scratch[(size_t)Bc * Hc * Sc * Sc];

// ---------------------------------------------------------------------------
// TF32 helpers (mma.sync.m16n8k8, standard fragment layouts)
// ---------------------------------------------------------------------------
__device__ __forceinline__ uint32_t f2tf(float f) {
    uint32_t u;
    asm("cvt.rna.tf32.f32 %0, %1;" : "=r"(u) : "f"(f));
    return u;
}

__device__ __forceinline__ void mma8(float c[4],
                                     uint32_t a0, uint32_t a1, uint32_t a2, uint32_t a3,
                                     uint32_t b0, uint32_t b1) {
    asm volatile(
        "mma.sync.aligned.m16n8k8.row.col.f32.tf32.tf32.f32 "
        "{%0,%1,%2,%3}, {%4,%5,%6,%7}, {%8,%9}, {%0,%1,%2,%3};"
        : "+f"(c[0]), "+f"(c[1]), "+f"(c[2]), "+f"(c[3])
        : "r"(a0), "r"(a1), "r"(a2), "r"(a3), "r"(b0), "r"(b1));
}

// ---------------------------------------------------------------------------
// TF32 tensor-core GEMM + bias: C[M,N] = A[M,K] @ W[K,N] + b[N]
// CTA tile 128x128, BK=32, 256 threads (8 warps 2x4), warp tile 64x32.
// ---------------------------------------------------------------------------
__global__ __launch_bounds__(256) void gemm_bias_tc(const float* __restrict__ A,
                                                    const float* __restrict__ W,
                                                    const float* __restrict__ bias,
                                                    float* __restrict__ C,
                                                    int M, int N, int K) {
    __shared__ uint32_t As[128 * 36];
    __shared__ uint32_t Bs[32 * 132];

    const int tid = threadIdx.x;
    const int w = tid >> 5, lane = tid & 31;
    const int g = lane >> 2, t = lane & 3;
    const int m0 = blockIdx.x * 128, n0 = blockIdx.y * 128;
    const int wm = (w & 1) * 64;
    const int wn = (w >> 1) * 32;

    float acc[4][4][4] = {};

    for (int k0 = 0; k0 < K; k0 += 32) {
#pragma unroll
        for (int i = 0; i < 4; i++) {
            int idx = tid + i * 256;
            int r = idx >> 3, c4 = idx & 7;
            float4 v = *(const float4*)&A[(size_t)(m0 + r) * K + k0 + c4 * 4];
            uint32_t* p = &As[r * 36 + c4 * 4];
            p[0] = f2tf(v.x); p[1] = f2tf(v.y); p[2] = f2tf(v.z); p[3] = f2tf(v.w);
        }
#pragma unroll
        for (int i = 0; i < 4; i++) {
            int idx = tid + i * 256;
            int r = idx >> 5, c4 = idx & 31;
            float4 v = *(const float4*)&W[(size_t)(k0 + r) * N + n0 + c4 * 4];
            uint32_t* p = &Bs[r * 132 + c4 * 4];
            p[0] = f2tf(v.x); p[1] = f2tf(v.y); p[2] = f2tf(v.z); p[3] = f2tf(v.w);
        }
        __syncthreads();

#pragma unroll
        for (int ks = 0; ks < 4; ks++) {
            uint32_t a[4][4], bb[4][2];
#pragma unroll
            for (int mf = 0; mf < 4; mf++) {
                int r = wm + mf * 16 + g;
                a[mf][0] = As[r * 36 + ks * 8 + t];
                a[mf][2] = As[r * 36 + ks * 8 + t + 4];
                a[mf][1] = As[(r + 8) * 36 + ks * 8 + t];
                a[mf][3] = As[(r + 8) * 36 + ks * 8 + t + 4];
            }
#pragma unroll
            for (int nf = 0; nf < 4; nf++) {
                bb[nf][0] = Bs[(ks * 8 + t) * 132 + wn + nf * 8 + g];
                bb[nf][1] = Bs[(ks * 8 + t + 4) * 132 + wn + nf * 8 + g];
            }
#pragma unroll
            for (int mf = 0; mf < 4; mf++)
#pragma unroll
                for (int nf = 0; nf < 4; nf++)
                    mma8(acc[mf][nf], a[mf][0], a[mf][1], a[mf][2], a[mf][3],
                         bb[nf][0], bb[nf][1]);
        }
        __syncthreads();
    }

#pragma unroll
    for (int mf = 0; mf < 4; mf++) {
#pragma unroll
        for (int nf = 0; nf < 4; nf++) {
            int col = n0 + wn + nf * 8 + 2 * t;
            float b0v = bias[col], b1v = bias[col + 1];
            int row = m0 + wm + mf * 16 + g;
            float2 v0 = {acc[mf][nf][0] + b0v, acc[mf][nf][1] + b1v};
            *(float2*)&C[(size_t)row * N + col] = v0;
            float2 v1 = {acc[mf][nf][2] + b0v, acc[mf][nf][3] + b1v};
            *(float2*)&C[(size_t)(row + 8) * N + col] = v1;
        }
    }
}

// ---------------------------------------------------------------------------
// Single-pass flash attention, TF32. Per (b, h, 64-query tile).
// Slab = 64 keys, 32 slabs. Online softmax with accumulator rescaling.
// Writes: raw scaled scores -> attn buffer, per-row (m,l) -> g_mbuf/g_lbuf,
//         context / l -> g_ctx.  Register prefetch of next K/V slab.
// Smem (32-bit words): Qs[64*68] Ks[64*68] Vs[64*68] Ps/Sf[64*68] srow lrow
// ---------------------------------------------------------------------------
#define AQ   0
#define AK   4352
#define AV   8704
#define AP   13056
#define ASR  17408
#define ALR  17472
#define AWORDS 17536
#define ATTN_SMEM_BYTES (AWORDS * 4)

__global__ __launch_bounds__(256, 2) void attn_flash(float* __restrict__ attn) {
    extern __shared__ uint32_t sh[];
    uint32_t* Qs = sh + AQ;            // tf32 Q [q][d] stride 68
    uint32_t* Ks = sh + AK;            // tf32 K [key][d] stride 68
    uint32_t* Vs = sh + AV;            // tf32 V [key][d] stride 68
    uint32_t* Ps = sh + AP;            // tf32 P [q][key] stride 68
    float*    Sf = (float*)Ps;         // fp32 scores, same buffer
    float*    srow = (float*)(sh + ASR);  // per-row rescale factor (slab)
    float*    lrow = (float*)(sh + ALR);  // per-row final l

    const int tid = threadIdx.x;
    const int w = tid >> 5, lane = tid & 31;
    const int g = lane >> 2, t = lane & 3;
    const int b = blockIdx.z, h = blockIdx.y, q0 = blockIdx.x << 6;
    const int qr = tid >> 2, qg = tid & 3;   // stats map: row, quarter
    const float scale = 0.125f;

    const int row_g = ((b * Hc + h) * Sc + q0);        // global attn row base
    float* attn_base = attn + (size_t)row_g * Sc;
    const float* kbase = g_k + ((size_t)b * Sc) * Dc + h * HDc;
    const float* vbase = g_v + ((size_t)b * Sc) * Dc + h * HDc;

    const int r0 = tid >> 4, c4 = tid & 15;  // staging map: 4 rows (r0+16i), 4 cols

    // Stage Q tile 64x64 (tf32)
#pragma unroll
    for (int i = 0; i < 4; i++) {
        int r = r0 + 16 * i;
        float4 v = *(const float4*)&g_q[((size_t)b * Sc + q0 + r) * Dc + h * HDc + c4 * 4];
        uint32_t* p = &Qs[r * 68 + c4 * 4];
        p[0] = f2tf(v.x); p[1] = f2tf(v.y); p[2] = f2tf(v.z); p[3] = f2tf(v.w);
    }

    // Prefetch slab 0 into registers and stage it
    float4 kv[4], vv[4];
#pragma unroll
    for (int i = 0; i < 4; i++) {
        int r = r0 + 16 * i;
        kv[i] = *(const float4*)&kbase[(size_t)r * Dc + c4 * 4];
        vv[i] = *(const float4*)&vbase[(size_t)r * Dc + c4 * 4];
    }
#pragma unroll
    for (int i = 0; i < 4; i++) {
        int r = r0 + 16 * i;
        uint32_t* pk = &Ks[r * 68 + c4 * 4];
        pk[0] = f2tf(kv[i].x); pk[1] = f2tf(kv[i].y); pk[2] = f2tf(kv[i].z); pk[3] = f2tf(kv[i].w);
        uint32_t* pv = &Vs[r * 68 + c4 * 4];
        pv[0] = f2tf(vv[i].x); pv[1] = f2tf(vv[i].y); pv[2] = f2tf(vv[i].z); pv[3] = f2tf(vv[i].w);
    }

    // Score warp map: 2(q) x 4(key) -> warp tile 32q x 16k
    const int wm1 = (w & 1) * 32;
    const int wn1 = (w >> 1) * 16;
    // PV warp map: 2(q) x 2(d) x 2(k-split)
    const int pm = (w & 1) * 32;
    const int pn = ((w >> 1) & 1) * 32;
    const int pk0 = (w >> 2) * 32;

    float m = -INFINITY, l_lane = 0.0f;
    float acc[2][4][4] = {};

    for (int s = 0; s < 32; s++) {
        __syncthreads();  // staged K/V/ (and prior-iter smem reads) visible

        // Prefetch next slab (LDG latency hidden under compute below)
        if (s + 1 < 32) {
            const int kk = (s + 1) << 6;
#pragma unroll
            for (int i = 0; i < 4; i++) {
                int r = kk + r0 + 16 * i;
                kv[i] = *(const float4*)&kbase[(size_t)r * Dc + c4 * 4];
                vv[i] = *(const float4*)&vbase[(size_t)r * Dc + c4 * 4];
            }
        }

        // ---- Scores: S = Q K^T (64q x 64k), per warp 32x16 ----
        float c[2][2][4] = {};
#pragma unroll
        for (int ks = 0; ks < 8; ks++) {
            uint32_t a[2][4], bb[2][2];
#pragma unroll
            for (int mf = 0; mf < 2; mf++) {
                int r = wm1 + mf * 16 + g;
                a[mf][0] = Qs[r * 68 + ks * 8 + t];
                a[mf][2] = Qs[r * 68 + ks * 8 + t + 4];
                a[mf][1] = Qs[(r + 8) * 68 + ks * 8 + t];
                a[mf][3] = Qs[(r + 8) * 68 + ks * 8 + t + 4];
            }
#pragma unroll
            for (int nf = 0; nf < 2; nf++) {
                int kr = wn1 + nf * 8 + g;
                bb[nf][0] = Ks[kr * 68 + ks * 8 + t];
                bb[nf][1] = Ks[kr * 68 + ks * 8 + t + 4];
            }
#pragma unroll
            for (int mf = 0; mf < 2; mf++)
#pragma unroll
                for (int nf = 0; nf < 2; nf++)
                    mma8(c[mf][nf], a[mf][0], a[mf][1], a[mf][2], a[mf][3],
                         bb[nf][0], bb[nf][1]);
        }
#pragma unroll
        for (int mf = 0; mf < 2; mf++)
#pragma unroll
            for (int nf = 0; nf < 2; nf++) {
                int row = wm1 + mf * 16 + g, col = wn1 + nf * 8 + 2 * t;
                float2 v0 = {c[mf][nf][0] * scale, c[mf][nf][1] * scale};
                *(float2*)&Sf[row * 68 + col] = v0;
                float2 v1 = {c[mf][nf][2] * scale, c[mf][nf][3] * scale};
                *(float2*)&Sf[(row + 8) * 68 + col] = v1;
            }
        __syncthreads();

        // ---- Stats (row qr, 16 cols per lane) ----
        // Phase 1: raw write to global + slab max
        float tmax = -INFINITY;
#pragma unroll
        for (int j = 0; j < 4; j++) {
            float4 v = *(const float4*)&Sf[qr * 68 + qg * 16 + j * 4];
            *(float4*)&attn_base[(size_t)qr * Sc + (s << 6) + qg * 16 + j * 4] = v;
            tmax = fmaxf(tmax, fmaxf(fmaxf(v.x, v.y), fmaxf(v.z, v.w)));
        }
        tmax = fmaxf(tmax, __shfl_xor_sync(0xffffffffu, tmax, 1));
        tmax = fmaxf(tmax, __shfl_xor_sync(0xffffffffu, tmax, 2));
        const float m_new = fmaxf(m, tmax);
        const float f = __expf(m - m_new);   // first slab: exp(-inf)=0
        // Phase 2: p = exp(s - m_new) -> tf32 in place; l update
        float ls = 0.0f;
#pragma unroll
        for (int j = 0; j < 4; j++) {
            float4 v = *(const float4*)&Sf[qr * 68 + qg * 16 + j * 4];
            float p0 = __expf(v.x - m_new), p1 = __expf(v.y - m_new);
            float p2 = __expf(v.z - m_new), p3 = __expf(v.w - m_new);
            ls += p0 + p1 + p2 + p3;
            uint32_t* p = &Ps[qr * 68 + qg * 16 + j * 4];
            p[0] = f2tf(p0); p[1] = f2tf(p1); p[2] = f2tf(p2); p[3] = f2tf(p3);
        }
        l_lane = l_lane * f + ls;
        m = m_new;
        if (qg == 0) srow[qr] = f;
        __syncthreads();

        // ---- Rescale acc + P@V (split-K halves across warp pairs) ----
#pragma unroll
        for (int mf = 0; mf < 2; mf++) {
            float f0 = srow[pm + mf * 16 + g];
            float f1 = srow[pm + mf * 16 + g + 8];
#pragma unroll
            for (int nf = 0; nf < 4; nf++) {
                acc[mf][nf][0] *= f0; acc[mf][nf][1] *= f0;
                acc[mf][nf][2] *= f1; acc[mf][nf][3] *= f1;
            }
        }
#pragma unroll
        for (int ks = 0; ks < 4; ks++) {
            const int kb = pk0 + ks * 8;
            uint32_t a[2][4], bb[4][2];
#pragma unroll
            for (int mf = 0; mf < 2; mf++) {
                int r = pm + mf * 16 + g;
                a[mf][0] = Ps[r * 68 + kb + t];
                a[mf][2] = Ps[r * 68 + kb + t + 4];
                a[mf][1] = Ps[(r + 8) * 68 + kb + t];
                a[mf][3] = Ps[(r + 8) * 68 + kb + t + 4];
            }
#pragma unroll
            for (int nf = 0; nf < 4; nf++) {
                bb[nf][0] = Vs[(kb + t) * 68 + pn + nf * 8 + g];
                bb[nf][1] = Vs[(kb + t + 4) * 68 + pn + nf * 8 + g];
            }
#pragma unroll
            for (int mf = 0; mf < 2; mf++)
#pragma unroll
                for (int nf = 0; nf < 4; nf++)
                    mma8(acc[mf][nf], a[mf][0], a[mf][1], a[mf][2], a[mf][3],
                         bb[nf][0], bb[nf][1]);
        }
        __syncthreads();  // all smem reads of this slab done

        // Stage prefetched next slab
        if (s + 1 < 32) {
#pragma unroll
            for (int i = 0; i < 4; i++) {
                int r = r0 + 16 * i;
                uint32_t* pkx = &Ks[r * 68 + c4 * 4];
                pkx[0] = f2tf(kv[i].x); pkx[1] = f2tf(kv[i].y);
                pkx[2] = f2tf(kv[i].z); pkx[3] = f2tf(kv[i].w);
                uint32_t* pvx = &Vs[r * 68 + c4 * 4];
                pvx[0] = f2tf(vv[i].x); pvx[1] = f2tf(vv[i].y);
                pvx[2] = f2tf(vv[i].z); pvx[3] = f2tf(vv[i].w);
            }
        }
    }

    // Final per-row l, write (m, l) for the normalize kernel
    float l_row = l_lane;
    l_row += __shfl_xor_sync(0xffffffffu, l_row, 1);
    l_row += __shfl_xor_sync(0xffffffffu, l_row, 2);
    if (qg == 0) {
        lrow[qr] = l_row;
        g_lbuf[row_g + qr] = l_row;
        g_mbuf[row_g + qr] = m;
    }
    __syncthreads();

    // Split-K reduce (warp w and w+4 share (pm,pn)): stage in Qs region (fp32)
    float* stage = (float*)Qs;
    if (w >= 4) {
#pragma unroll
        for (int mf = 0; mf < 2; mf++)
#pragma unroll
            for (int nf = 0; nf < 4; nf++) {
                int row = pm + mf * 16 + g, col = pn + nf * 8 + 2 * t;
                *(float2*)&stage[row * 68 + col] =
                    make_float2(acc[mf][nf][0], acc[mf][nf][1]);
                *(float2*)&stage[(row + 8) * 68 + col] =
                    make_float2(acc[mf][nf][2], acc[mf][nf][3]);
            }
    }
    __syncthreads();
    if (w < 4) {
#pragma unroll
        for (int mf = 0; mf < 2; mf++)
#pragma unroll
            for (int nf = 0; nf < 4; nf++) {
                int row = pm + mf * 16 + g, col = pn + nf * 8 + 2 * t;
                float il0 = 1.0f / lrow[row], il1 = 1.0f / lrow[row + 8];
                float2 o0 = *(const float2*)&stage[row * 68 + col];
                float2 o1 = *(const float2*)&stage[(row + 8) * 68 + col];
                o0.x = (o0.x + acc[mf][nf][0]) * il0;
                o0.y = (o0.y + acc[mf][nf][1]) * il0;
                o1.x = (o1.x + acc[mf][nf][2]) * il1;
                o1.y = (o1.y + acc[mf][nf][3]) * il1;
                *(float2*)&g_ctx[((size_t)b * Sc + q0 + row) * Dc + h * HDc + col] = o0;
                *(float2*)&g_ctx[((size_t)b * Sc + q0 + row + 8) * Dc + h * HDc + col] = o1;
            }
    }
}

// ---------------------------------------------------------------------------
// Streaming normalize: attn[i] = exp(raw - m_row) / l_row  (in place)
// ---------------------------------------------------------------------------
__global__ __launch_bounds__(256) void normalize_attn(float* __restrict__ attn) {
    size_t i4 = (size_t)blockIdx.x * 256 + threadIdx.x;  // float4 index
    int row = (int)(i4 >> 9);                            // 512 float4 per row
    float mm = g_mbuf[row];
    float il = 1.0f / g_lbuf[row];
    float4 v = *((const float4*)attn + i4);
    v.x = __expf(v.x - mm) * il;
    v.y = __expf(v.y - mm) * il;
    v.z = __expf(v.z - mm) * il;
    v.w = __expf(v.w - mm) * il;
    *((float4*)attn + i4) = v;
}

// ---------------------------------------------------------------------------
extern "C" void kernel_launch(void* const* d_in, const int* in_sizes, int n_in,
                              void* d_out, int out_size) {
    const float* query = (const float*)d_in[0];
    const float* key_  = (const float*)d_in[1];
    const float* value = (const float*)d_in[2];
    const float* Wq = (const float*)d_in[3];
    const float* bq = (const float*)d_in[4];
    const float* Wk = (const float*)d_in[5];
    const float* bk = (const float*)d_in[6];
    const float* Wv = (const float*)d_in[7];
    const float* bv = (const float*)d_in[8];
    const float* Wo = (const float*)d_in[9];
    const float* bo = (const float*)d_in[10];
    float* out = (float*)d_out;

    float *dq, *dk, *dv, *dctx;
    cudaGetSymbolAddress((void**)&dq,  g_q);
    cudaGetSymbolAddress((void**)&dk,  g_k);
    cudaGetSymbolAddress((void**)&dv,  g_v);
    cudaGetSymbolAddress((void**)&dctx, g_ctx);

    const size_t OUT_ELEMS  = (size_t)Bc * Sc * Dc;           // 4,194,304
    const size_t ATTN_ELEMS = (size_t)Bc * Hc * Sc * Sc;      // 134,217,728
    float* attn_ptr;
    if ((size_t)out_size >= OUT_ELEMS + ATTN_ELEMS) {
        attn_ptr = out + OUT_ELEMS;
    } else {
        cudaGetSymbolAddress((void**)&attn_ptr, g_attn_scratch);
    }

    cudaFuncSetAttribute(attn_flash,
                         cudaFuncAttributeMaxDynamicSharedMemorySize,
                         ATTN_SMEM_BYTES);

    dim3 ggrid(BSc / 128, Dc / 128);  // 32 x 8

    gemm_bias_tc<<<ggrid, 256>>>(query, Wq, bq, dq, BSc, Dc, Dc);
    gemm_bias_tc<<<ggrid, 256>>>(key_,  Wk, bk, dk, BSc, Dc, Dc);
    gemm_bias_tc<<<ggrid, 256>>>(value, Wv, bv, dv, BSc, Dc, Dc);

    attn_flash<<<dim3(Sc / 64, Hc, Bc), 256, ATTN_SMEM_BYTES>>>(attn_ptr);

    // Normalize attn probabilities (raw -> softmax), pure streaming
    normalize_attn<<<(unsigned)(ATTN_ELEMS / 4 / 256), 256>>>(attn_ptr);

    gemm_bias_tc<<<ggrid, 256>>>(dctx, Wo, bo, out, BSc, Dc, Dc);
}

// round 7
// speedup vs baseline: 2.3309x; 1.0783x over previous
#include <cuda_runtime.h>
#include <math.h>
#include <stdint.h>

// Problem constants
#define Bc  2
#define Sc  2048
#define Dc  1024
#define Hc  16
#define HDc 64
#define BSc (Bc * Sc)
#define BHS (Bc * Hc * Sc)   // 65536 attention rows

// Scratch (device globals; allocation inside kernel_launch is forbidden)
__device__ float g_q[(size_t)Bc * Sc * Dc];
__device__ float g_k[(size_t)Bc * Sc * Dc];
__device__ float g_v[(size_t)Bc * Sc * Dc];
__device__ float g_ctx[(size_t)Bc * Sc * Dc];
__device__ float g_mbuf[BHS];
__device__ float g_lbuf[BHS];
__device__ float g_attn_scratch[(size_t)Bc * Hc * Sc * Sc];

// ---------------------------------------------------------------------------
// TF32 helpers (mma.sync.m16n8k8, standard fragment layouts)
// ---------------------------------------------------------------------------
__device__ __forceinline__ uint32_t f2tf(float f) {
    uint32_t u;
    asm("cvt.rna.tf32.f32 %0, %1;" : "=r"(u) : "f"(f));
    return u;
}

__device__ __forceinline__ void mma8(float c[4],
                                     uint32_t a0, uint32_t a1, uint32_t a2, uint32_t a3,
                                     uint32_t b0, uint32_t b1) {
    asm volatile(
        "mma.sync.aligned.m16n8k8.row.col.f32.tf32.tf32.f32 "
        "{%0,%1,%2,%3}, {%4,%5,%6,%7}, {%8,%9}, {%0,%1,%2,%3};"
        : "+f"(c[0]), "+f"(c[1]), "+f"(c[2]), "+f"(c[3])
        : "r"(a0), "r"(a1), "r"(a2), "r"(a3), "r"(b0), "r"(b1));
}

// ---------------------------------------------------------------------------
// TF32 tensor-core GEMM + bias: C[M,N] = A[M,K] @ W[K,N] + b[N]
// CTA tile 128x128, BK=32, 256 threads (8 warps 2x4), warp tile 64x32.
// ---------------------------------------------------------------------------
__global__ __launch_bounds__(256) void gemm_bias_tc(const float* __restrict__ A,
                                                    const float* __restrict__ W,
                                                    const float* __restrict__ bias,
                                                    float* __restrict__ C,
                                                    int M, int N, int K) {
    __shared__ uint32_t As[128 * 36];
    __shared__ uint32_t Bs[32 * 132];

    const int tid = threadIdx.x;
    const int w = tid >> 5, lane = tid & 31;
    const int g = lane >> 2, t = lane & 3;
    const int m0 = blockIdx.x * 128, n0 = blockIdx.y * 128;
    const int wm = (w & 1) * 64;
    const int wn = (w >> 1) * 32;

    float acc[4][4][4] = {};

    for (int k0 = 0; k0 < K; k0 += 32) {
#pragma unroll
        for (int i = 0; i < 4; i++) {
            int idx = tid + i * 256;
            int r = idx >> 3, c4 = idx & 7;
            float4 v = *(const float4*)&A[(size_t)(m0 + r) * K + k0 + c4 * 4];
            uint32_t* p = &As[r * 36 + c4 * 4];
            p[0] = f2tf(v.x); p[1] = f2tf(v.y); p[2] = f2tf(v.z); p[3] = f2tf(v.w);
        }
#pragma unroll
        for (int i = 0; i < 4; i++) {
            int idx = tid + i * 256;
            int r = idx >> 5, c4 = idx & 31;
            float4 v = *(const float4*)&W[(size_t)(k0 + r) * N + n0 + c4 * 4];
            uint32_t* p = &Bs[r * 132 + c4 * 4];
            p[0] = f2tf(v.x); p[1] = f2tf(v.y); p[2] = f2tf(v.z); p[3] = f2tf(v.w);
        }
        __syncthreads();

#pragma unroll
        for (int ks = 0; ks < 4; ks++) {
            uint32_t a[4][4], bb[4][2];
#pragma unroll
            for (int mf = 0; mf < 4; mf++) {
                int r = wm + mf * 16 + g;
                a[mf][0] = As[r * 36 + ks * 8 + t];
                a[mf][2] = As[r * 36 + ks * 8 + t + 4];
                a[mf][1] = As[(r + 8) * 36 + ks * 8 + t];
                a[mf][3] = As[(r + 8) * 36 + ks * 8 + t + 4];
            }
#pragma unroll
            for (int nf = 0; nf < 4; nf++) {
                bb[nf][0] = Bs[(ks * 8 + t) * 132 + wn + nf * 8 + g];
                bb[nf][1] = Bs[(ks * 8 + t + 4) * 132 + wn + nf * 8 + g];
            }
#pragma unroll
            for (int mf = 0; mf < 4; mf++)
#pragma unroll
                for (int nf = 0; nf < 4; nf++)
                    mma8(acc[mf][nf], a[mf][0], a[mf][1], a[mf][2], a[mf][3],
                         bb[nf][0], bb[nf][1]);
        }
        __syncthreads();
    }

#pragma unroll
    for (int mf = 0; mf < 4; mf++) {
#pragma unroll
        for (int nf = 0; nf < 4; nf++) {
            int col = n0 + wn + nf * 8 + 2 * t;
            float b0v = bias[col], b1v = bias[col + 1];
            int row = m0 + wm + mf * 16 + g;
            float2 v0 = {acc[mf][nf][0] + b0v, acc[mf][nf][1] + b1v};
            *(float2*)&C[(size_t)row * N + col] = v0;
            float2 v1 = {acc[mf][nf][2] + b0v, acc[mf][nf][3] + b1v};
            *(float2*)&C[(size_t)(row + 8) * N + col] = v1;
        }
    }
}

// ---------------------------------------------------------------------------
// Flash attention v2: 128-query CTA tile, TF32, register epilogue.
// Per (b, h, 128-query tile); 32 slabs of 64 keys.
// Warp map (both phases): (w&3) -> 32-q block, (w>>2) -> 32-k / 32-d block.
// Raw scaled scores STG'd straight from fragments; softmax stats built from
// registers via in-quad shuffles + cross-warp smem combine; P stored once,
// transposed (stride 136, conflict-free PV fragment reads).
// Smem words: Qs[128*68] Ks[64*68] Vs[64*72] PsT[64*136] wmax[256] wsum[256]
//             mrow[128] srow[128] lrow[128]  = 27264 words = 109056 B
// ---------------------------------------------------------------------------
#define AQ    0
#define AK    8704
#define AV    13056
#define APT   17664
#define AWMAX 26368
#define AWSUM 26624
#define AMR   26880
#define ASR   27008
#define ALR   27136
#define AWORDS 27264
#define ATTN_SMEM_BYTES (AWORDS * 4)

__global__ __launch_bounds__(256, 2) void attn_flash(float* __restrict__ attn) {
    extern __shared__ uint32_t sh[];
    uint32_t* Qs  = sh + AQ;              // tf32 Q [q][d] stride 68 (pre-scaled)
    uint32_t* Ks  = sh + AK;              // tf32 K [key][d] stride 68
    uint32_t* Vs  = sh + AV;              // tf32 V [key][d] stride 72
    uint32_t* Ps  = sh + APT;             // tf32 P^T [key][q] stride 136
    float* wmax = (float*)(sh + AWMAX);   // [2][128] per-warp-side row max
    float* wsum = (float*)(sh + AWSUM);   // [2][128] per-warp-side row sum
    float* mrow = (float*)(sh + AMR);     // running row max
    float* srow = (float*)(sh + ASR);     // slab rescale factor
    float* lrow = (float*)(sh + ALR);     // running row sum

    const int tid = threadIdx.x;
    const int w = tid >> 5, lane = tid & 31;
    const int g = lane >> 2, t = lane & 3;
    const int b = blockIdx.z, h = blockIdx.y, q0 = blockIdx.x << 7;

    const int row_g = (b * Hc + h) * Sc + q0;
    float* attn_base = attn + (size_t)row_g * Sc;
    const float* kbase = g_k + ((size_t)b * Sc) * Dc + h * HDc;
    const float* vbase = g_v + ((size_t)b * Sc) * Dc + h * HDc;

    const int r0 = tid >> 4, c4 = tid & 15;  // K/V staging map

    if (tid < 128) { mrow[tid] = -INFINITY; lrow[tid] = 0.0f; }

    // Stage Q 128x64 (tf32, pre-scaled by 1/sqrt(64))
#pragma unroll
    for (int i = 0; i < 8; i++) {
        int idx = tid + i * 256;
        int r = idx >> 4, cc = idx & 15;
        float4 v = *(const float4*)&g_q[((size_t)b * Sc + q0 + r) * Dc + h * HDc + cc * 4];
        uint32_t* p = &Qs[r * 68 + cc * 4];
        p[0] = f2tf(v.x * 0.125f); p[1] = f2tf(v.y * 0.125f);
        p[2] = f2tf(v.z * 0.125f); p[3] = f2tf(v.w * 0.125f);
    }

    // Prefetch + stage slab 0
    float4 kv[4], vv[4];
#pragma unroll
    for (int i = 0; i < 4; i++) {
        int r = r0 + 16 * i;
        kv[i] = *(const float4*)&kbase[(size_t)r * Dc + c4 * 4];
        vv[i] = *(const float4*)&vbase[(size_t)r * Dc + c4 * 4];
    }
#pragma unroll
    for (int i = 0; i < 4; i++) {
        int r = r0 + 16 * i;
        uint32_t* pk = &Ks[r * 68 + c4 * 4];
        pk[0] = f2tf(kv[i].x); pk[1] = f2tf(kv[i].y); pk[2] = f2tf(kv[i].z); pk[3] = f2tf(kv[i].w);
        uint32_t* pv = &Vs[r * 72 + c4 * 4];
        pv[0] = f2tf(vv[i].x); pv[1] = f2tf(vv[i].y); pv[2] = f2tf(vv[i].z); pv[3] = f2tf(vv[i].w);
    }

    const int wq = (w & 3) * 32;    // q block (both phases)
    const int wk = (w >> 2) * 32;   // score: k block; PV: d block
    const int side = w >> 2;

    float acc[2][4][4] = {};

    for (int s = 0; s < 32; s++) {
        __syncthreads();   // staged K/V visible; prior Ps reads done

        // Prefetch next K (V prefetched after score phase)
        if (s + 1 < 32) {
            const int kk = (s + 1) << 6;
#pragma unroll
            for (int i = 0; i < 4; i++)
                kv[i] = *(const float4*)&kbase[(size_t)(kk + r0 + 16 * i) * Dc + c4 * 4];
        }

        // ---- Score MMA: warp 32q x 32k over d=64 ----
        float c[2][4][4] = {};
#pragma unroll
        for (int ks = 0; ks < 8; ks++) {
            uint32_t a[2][4], bb[4][2];
#pragma unroll
            for (int mf = 0; mf < 2; mf++) {
                int r = wq + mf * 16 + g;
                a[mf][0] = Qs[r * 68 + ks * 8 + t];
                a[mf][1] = Qs[(r + 8) * 68 + ks * 8 + t];
                a[mf][2] = Qs[r * 68 + ks * 8 + t + 4];
                a[mf][3] = Qs[(r + 8) * 68 + ks * 8 + t + 4];
            }
#pragma unroll
            for (int nf = 0; nf < 4; nf++) {
                int kr = wk + nf * 8 + g;
                bb[nf][0] = Ks[kr * 68 + ks * 8 + t];
                bb[nf][1] = Ks[kr * 68 + ks * 8 + t + 4];
            }
#pragma unroll
            for (int mf = 0; mf < 2; mf++)
#pragma unroll
                for (int nf = 0; nf < 4; nf++)
                    mma8(c[mf][nf], a[mf][0], a[mf][1], a[mf][2], a[mf][3],
                         bb[nf][0], bb[nf][1]);
        }

        // Prefetch next V
        if (s + 1 < 32) {
            const int kk = (s + 1) << 6;
#pragma unroll
            for (int i = 0; i < 4; i++)
                vv[i] = *(const float4*)&vbase[(size_t)(kk + r0 + 16 * i) * Dc + c4 * 4];
        }

        // ---- Register epilogue: raw STG + row max ----
        float mx[2][2];
#pragma unroll
        for (int mf = 0; mf < 2; mf++) {
            mx[mf][0] = -INFINITY; mx[mf][1] = -INFINITY;
            int row = wq + mf * 16 + g;
#pragma unroll
            for (int nf = 0; nf < 4; nf++) {
                int col = (s << 6) + wk + nf * 8 + 2 * t;
                *(float2*)&attn_base[(size_t)row * Sc + col] =
                    make_float2(c[mf][nf][0], c[mf][nf][1]);
                *(float2*)&attn_base[(size_t)(row + 8) * Sc + col] =
                    make_float2(c[mf][nf][2], c[mf][nf][3]);
                mx[mf][0] = fmaxf(mx[mf][0], fmaxf(c[mf][nf][0], c[mf][nf][1]));
                mx[mf][1] = fmaxf(mx[mf][1], fmaxf(c[mf][nf][2], c[mf][nf][3]));
            }
#pragma unroll
            for (int d = 1; d < 4; d <<= 1) {
                mx[mf][0] = fmaxf(mx[mf][0], __shfl_xor_sync(0xffffffffu, mx[mf][0], d));
                mx[mf][1] = fmaxf(mx[mf][1], __shfl_xor_sync(0xffffffffu, mx[mf][1], d));
            }
            if (t == 0) {
                wmax[side * 128 + row] = mx[mf][0];
                wmax[side * 128 + row + 8] = mx[mf][1];
            }
        }
        __syncthreads();

        // ---- Row combine: m_new, rescale factor ----
        if (tid < 128) {
            float mn = fmaxf(mrow[tid], fmaxf(wmax[tid], wmax[128 + tid]));
            srow[tid] = __expf(mrow[tid] - mn);   // first slab: exp(-inf)=0
            mrow[tid] = mn;
        }
        __syncthreads();

        // ---- exp in regs, P^T store, row sums ----
#pragma unroll
        for (int mf = 0; mf < 2; mf++) {
            int row = wq + mf * 16 + g;
            float mn0 = mrow[row], mn1 = mrow[row + 8];
            float s0 = 0.0f, s1 = 0.0f;
#pragma unroll
            for (int nf = 0; nf < 4; nf++) {
                float p0 = __expf(c[mf][nf][0] - mn0);
                float p1 = __expf(c[mf][nf][1] - mn0);
                float p2 = __expf(c[mf][nf][2] - mn1);
                float p3 = __expf(c[mf][nf][3] - mn1);
                s0 += p0 + p1; s1 += p2 + p3;
                int col = wk + nf * 8 + 2 * t;
                Ps[col * 136 + row] = f2tf(p0);
                Ps[(col + 1) * 136 + row] = f2tf(p1);
                Ps[col * 136 + row + 8] = f2tf(p2);
                Ps[(col + 1) * 136 + row + 8] = f2tf(p3);
            }
#pragma unroll
            for (int d = 1; d < 4; d <<= 1) {
                s0 += __shfl_xor_sync(0xffffffffu, s0, d);
                s1 += __shfl_xor_sync(0xffffffffu, s1, d);
            }
            if (t == 0) {
                wsum[side * 128 + row] = s0;
                wsum[side * 128 + row + 8] = s1;
            }
        }
        __syncthreads();

        // l update (read only after the loop; no extra sync needed)
        if (tid < 128)
            lrow[tid] = lrow[tid] * srow[tid] + wsum[tid] + wsum[128 + tid];

        // ---- Rescale acc + PV MMA: warp 32q x 32d over k=64 ----
#pragma unroll
        for (int mf = 0; mf < 2; mf++) {
            float f0 = srow[wq + mf * 16 + g];
            float f1 = srow[wq + mf * 16 + g + 8];
#pragma unroll
            for (int nf = 0; nf < 4; nf++) {
                acc[mf][nf][0] *= f0; acc[mf][nf][1] *= f0;
                acc[mf][nf][2] *= f1; acc[mf][nf][3] *= f1;
            }
        }
#pragma unroll
        for (int ks = 0; ks < 8; ks++) {
            const int kb = ks * 8;
            uint32_t a[2][4], bb[4][2];
#pragma unroll
            for (int mf = 0; mf < 2; mf++) {
                int row = wq + mf * 16 + g;
                a[mf][0] = Ps[(kb + t) * 136 + row];
                a[mf][1] = Ps[(kb + t) * 136 + row + 8];
                a[mf][2] = Ps[(kb + t + 4) * 136 + row];
                a[mf][3] = Ps[(kb + t + 4) * 136 + row + 8];
            }
#pragma unroll
            for (int nf = 0; nf < 4; nf++) {
                bb[nf][0] = Vs[(kb + t) * 72 + wk + nf * 8 + g];
                bb[nf][1] = Vs[(kb + t + 4) * 72 + wk + nf * 8 + g];
            }
#pragma unroll
            for (int mf = 0; mf < 2; mf++)
#pragma unroll
                for (int nf = 0; nf < 4; nf++)
                    mma8(acc[mf][nf], a[mf][0], a[mf][1], a[mf][2], a[mf][3],
                         bb[nf][0], bb[nf][1]);
        }
        __syncthreads();   // all smem reads of this slab done

        // Stage prefetched next slab
        if (s + 1 < 32) {
#pragma unroll
            for (int i = 0; i < 4; i++) {
                int r = r0 + 16 * i;
                uint32_t* pk = &Ks[r * 68 + c4 * 4];
                pk[0] = f2tf(kv[i].x); pk[1] = f2tf(kv[i].y);
                pk[2] = f2tf(kv[i].z); pk[3] = f2tf(kv[i].w);
                uint32_t* pv = &Vs[r * 72 + c4 * 4];
                pv[0] = f2tf(vv[i].x); pv[1] = f2tf(vv[i].y);
                pv[2] = f2tf(vv[i].z); pv[3] = f2tf(vv[i].w);
            }
        }
    }
    __syncthreads();

    if (tid < 128) {
        g_mbuf[row_g + tid] = mrow[tid];
        g_lbuf[row_g + tid] = lrow[tid];
    }

    // Context epilogue: out = acc / l
#pragma unroll
    for (int mf = 0; mf < 2; mf++) {
        int row = wq + mf * 16 + g;
        float il0 = 1.0f / lrow[row], il1 = 1.0f / lrow[row + 8];
#pragma unroll
        for (int nf = 0; nf < 4; nf++) {
            int col = wk + nf * 8 + 2 * t;
            *(float2*)&g_ctx[((size_t)b * Sc + q0 + row) * Dc + h * HDc + col] =
                make_float2(acc[mf][nf][0] * il0, acc[mf][nf][1] * il0);
            *(float2*)&g_ctx[((size_t)b * Sc + q0 + row + 8) * Dc + h * HDc + col] =
                make_float2(acc[mf][nf][2] * il1, acc[mf][nf][3] * il1);
        }
    }
}

// ---------------------------------------------------------------------------
// Streaming normalize: attn[i] = exp(raw - m_row) / l_row  (in place)
// ---------------------------------------------------------------------------
__global__ __launch_bounds__(256) void normalize_attn(float* __restrict__ attn) {
    size_t i4 = (size_t)blockIdx.x * 256 + threadIdx.x;  // float4 index
    int row = (int)(i4 >> 9);                            // 512 float4 per row
    float mm = g_mbuf[row];
    float il = 1.0f / g_lbuf[row];
    float4 v = *((const float4*)attn + i4);
    v.x = __expf(v.x - mm) * il;
    v.y = __expf(v.y - mm) * il;
    v.z = __expf(v.z - mm) * il;
    v.w = __expf(v.w - mm) * il;
    *((float4*)attn + i4) = v;
}

// ---------------------------------------------------------------------------
extern "C" void kernel_launch(void* const* d_in, const int* in_sizes, int n_in,
                              void* d_out, int out_size) {
    const float* query = (const float*)d_in[0];
    const float* key_  = (const float*)d_in[1];
    const float* value = (const float*)d_in[2];
    const float* Wq = (const float*)d_in[3];
    const float* bq = (const float*)d_in[4];
    const float* Wk = (const float*)d_in[5];
    const float* bk = (const float*)d_in[6];
    const float* Wv = (const float*)d_in[7];
    const float* bv = (const float*)d_in[8];
    const float* Wo = (const float*)d_in[9];
    const float* bo = (const float*)d_in[10];
    float* out = (float*)d_out;

    float *dq, *dk, *dv, *dctx;
    cudaGetSymbolAddress((void**)&dq,  g_q);
    cudaGetSymbolAddress((void**)&dk,  g_k);
    cudaGetSymbolAddress((void**)&dv,  g_v);
    cudaGetSymbolAddress((void**)&dctx, g_ctx);

    const size_t OUT_ELEMS  = (size_t)Bc * Sc * Dc;           // 4,194,304
    const size_t ATTN_ELEMS = (size_t)Bc * Hc * Sc * Sc;      // 134,217,728
    float* attn_ptr;
    if ((size_t)out_size >= OUT_ELEMS + ATTN_ELEMS) {
        attn_ptr = out + OUT_ELEMS;
    } else {
        cudaGetSymbolAddress((void**)&attn_ptr, g_attn_scratch);
    }

    cudaFuncSetAttribute(attn_flash,
                         cudaFuncAttributeMaxDynamicSharedMemorySize,
                         ATTN_SMEM_BYTES);

    dim3 ggrid(BSc / 128, Dc / 128);  // 32 x 8

    gemm_bias_tc<<<ggrid, 256>>>(query, Wq, bq, dq, BSc, Dc, Dc);
    gemm_bias_tc<<<ggrid, 256>>>(key_,  Wk, bk, dk, BSc, Dc, Dc);
    gemm_bias_tc<<<ggrid, 256>>>(value, Wv, bv, dv, BSc, Dc, Dc);

    attn_flash<<<dim3(Sc / 128, Hc, Bc), 256, ATTN_SMEM_BYTES>>>(attn_ptr);

    // Normalize attn probabilities (raw -> softmax), pure streaming
    normalize_attn<<<(unsigned)(ATTN_ELEMS / 4 / 256), 256>>>(attn_ptr);

    gemm_bias_tc<<<ggrid, 256>>>(dctx, Wo, bo, out, BSc, Dc, Dc);
}

// round 8
// speedup vs baseline: 2.3358x; 1.0021x over previous
#include <cuda_runtime.h>
#include <math.h>
#include <stdint.h>

// Problem constants
#define Bc  2
#define Sc  2048
#define Dc  1024
#define Hc  16
#define HDc 64
#define BSc (Bc * Sc)
#define BHS (Bc * Hc * Sc)   // 65536 attention rows

// Scratch (device globals; allocation inside kernel_launch is forbidden)
__device__ float g_q[(size_t)Bc * Sc * Dc];
__device__ float g_k[(size_t)Bc * Sc * Dc];
__device__ float g_v[(size_t)Bc * Sc * Dc];
__device__ float g_ctx[(size_t)Bc * Sc * Dc];
__device__ float g_mbuf[BHS];
__device__ float g_lbuf[BHS];
__device__ float g_attn_scratch[(size_t)Bc * Hc * Sc * Sc];

// ---------------------------------------------------------------------------
// TF32 helpers (mma.sync.m16n8k8, standard fragment layouts)
// ---------------------------------------------------------------------------
__device__ __forceinline__ uint32_t f2tf(float f) {
    uint32_t u;
    asm("cvt.rna.tf32.f32 %0, %1;" : "=r"(u) : "f"(f));
    return u;
}

__device__ __forceinline__ void mma8(float c[4],
                                     uint32_t a0, uint32_t a1, uint32_t a2, uint32_t a3,
                                     uint32_t b0, uint32_t b1) {
    asm volatile(
        "mma.sync.aligned.m16n8k8.row.col.f32.tf32.tf32.f32 "
        "{%0,%1,%2,%3}, {%4,%5,%6,%7}, {%8,%9}, {%0,%1,%2,%3};"
        : "+f"(c[0]), "+f"(c[1]), "+f"(c[2]), "+f"(c[3])
        : "r"(a0), "r"(a1), "r"(a2), "r"(a3), "r"(b0), "r"(b1));
}

// ---------------------------------------------------------------------------
// TF32 tensor-core GEMM + bias: C[M,N] = A[M,K] @ W[K,N] + b[N]
// CTA tile 128x128, BK=32, 256 threads (8 warps 2x4), warp tile 64x32.
// ---------------------------------------------------------------------------
__global__ __launch_bounds__(256) void gemm_bias_tc(const float* __restrict__ A,
                                                    const float* __restrict__ W,
                                                    const float* __restrict__ bias,
                                                    float* __restrict__ C,
                                                    int M, int N, int K) {
    __shared__ uint32_t As[128 * 36];
    __shared__ uint32_t Bs[32 * 132];

    const int tid = threadIdx.x;
    const int w = tid >> 5, lane = tid & 31;
    const int g = lane >> 2, t = lane & 3;
    const int m0 = blockIdx.x * 128, n0 = blockIdx.y * 128;
    const int wm = (w & 1) * 64;
    const int wn = (w >> 1) * 32;

    float acc[4][4][4] = {};

    for (int k0 = 0; k0 < K; k0 += 32) {
#pragma unroll
        for (int i = 0; i < 4; i++) {
            int idx = tid + i * 256;
            int r = idx >> 3, c4 = idx & 7;
            float4 v = *(const float4*)&A[(size_t)(m0 + r) * K + k0 + c4 * 4];
            uint32_t* p = &As[r * 36 + c4 * 4];
            p[0] = f2tf(v.x); p[1] = f2tf(v.y); p[2] = f2tf(v.z); p[3] = f2tf(v.w);
        }
#pragma unroll
        for (int i = 0; i < 4; i++) {
            int idx = tid + i * 256;
            int r = idx >> 5, c4 = idx & 31;
            float4 v = *(const float4*)&W[(size_t)(k0 + r) * N + n0 + c4 * 4];
            uint32_t* p = &Bs[r * 132 + c4 * 4];
            p[0] = f2tf(v.x); p[1] = f2tf(v.y); p[2] = f2tf(v.z); p[3] = f2tf(v.w);
        }
        __syncthreads();

#pragma unroll
        for (int ks = 0; ks < 4; ks++) {
            uint32_t a[4][4], bb[4][2];
#pragma unroll
            for (int mf = 0; mf < 4; mf++) {
                int r = wm + mf * 16 + g;
                a[mf][0] = As[r * 36 + ks * 8 + t];
                a[mf][2] = As[r * 36 + ks * 8 + t + 4];
                a[mf][1] = As[(r + 8) * 36 + ks * 8 + t];
                a[mf][3] = As[(r + 8) * 36 + ks * 8 + t + 4];
            }
#pragma unroll
            for (int nf = 0; nf < 4; nf++) {
                bb[nf][0] = Bs[(ks * 8 + t) * 132 + wn + nf * 8 + g];
                bb[nf][1] = Bs[(ks * 8 + t + 4) * 132 + wn + nf * 8 + g];
            }
#pragma unroll
            for (int mf = 0; mf < 4; mf++)
#pragma unroll
                for (int nf = 0; nf < 4; nf++)
                    mma8(acc[mf][nf], a[mf][0], a[mf][1], a[mf][2], a[mf][3],
                         bb[nf][0], bb[nf][1]);
        }
        __syncthreads();
    }

#pragma unroll
    for (int mf = 0; mf < 4; mf++) {
#pragma unroll
        for (int nf = 0; nf < 4; nf++) {
            int col = n0 + wn + nf * 8 + 2 * t;
            float b0v = bias[col], b1v = bias[col + 1];
            int row = m0 + wm + mf * 16 + g;
            float2 v0 = {acc[mf][nf][0] + b0v, acc[mf][nf][1] + b1v};
            *(float2*)&C[(size_t)row * N + col] = v0;
            float2 v1 = {acc[mf][nf][2] + b0v, acc[mf][nf][3] + b1v};
            *(float2*)&C[(size_t)(row + 8) * N + col] = v1;
        }
    }
}

// ---------------------------------------------------------------------------
// Flash attention v3: 128-query CTA, warp-private softmax.
// Warp tile = 16 queries x ALL 64 keys -> row stats close in-quad (shuffles),
// no cross-warp combines, no stat smem. P tile per warp (16x68, row-major;
// PV A-frag reads hit banks 4g+t: conflict-free). 2 syncthreads + 1 syncwarp
// per slab. m/l live in registers.
// Smem words: Qs 128*68=8704 | Ks 64*68=4352 | Vs 64*72=4608 | Ps 8*1088=8704
//             total 26368 words = 105472 B
// ---------------------------------------------------------------------------
#define AQ    0
#define AK    8704
#define AV    13056
#define APT   17664
#define AWORDS 26368
#define ATTN_SMEM_BYTES (AWORDS * 4)

__global__ __launch_bounds__(256, 2) void attn_flash(float* __restrict__ attn) {
    extern __shared__ uint32_t sh[];
    uint32_t* Qs = sh + AQ;          // tf32 Q [q][d] stride 68 (pre-scaled)
    uint32_t* Ks = sh + AK;          // tf32 K [key][d] stride 68
    uint32_t* Vs = sh + AV;          // tf32 V [key][d] stride 72
    uint32_t* Ps = sh + APT;         // per-warp tf32 P [16 rows][64 cols] stride 68

    const int tid = threadIdx.x;
    const int w = tid >> 5, lane = tid & 31;
    const int g = lane >> 2, t = lane & 3;
    const int b = blockIdx.z, h = blockIdx.y, q0 = blockIdx.x << 7;
    const int wq = w * 16;           // this warp's query rows [wq, wq+16)

    const int row_g = (b * Hc + h) * Sc + q0;
    float* attn_base = attn + (size_t)row_g * Sc;
    const float* kbase = g_k + ((size_t)b * Sc) * Dc + h * HDc;
    const float* vbase = g_v + ((size_t)b * Sc) * Dc + h * HDc;

    const int r0 = tid >> 4, c4 = tid & 15;  // K/V staging map
    uint32_t* Pw = Ps + w * 1088;            // warp-private P tile

    // Stage Q 128x64 (tf32, pre-scaled by 1/sqrt(64))
#pragma unroll
    for (int i = 0; i < 8; i++) {
        int idx = tid + i * 256;
        int r = idx >> 4, cc = idx & 15;
        float4 v = *(const float4*)&g_q[((size_t)b * Sc + q0 + r) * Dc + h * HDc + cc * 4];
        uint32_t* p = &Qs[r * 68 + cc * 4];
        p[0] = f2tf(v.x * 0.125f); p[1] = f2tf(v.y * 0.125f);
        p[2] = f2tf(v.z * 0.125f); p[3] = f2tf(v.w * 0.125f);
    }

    // Prefetch + stage slab 0
    float4 kv[4], vv[4];
#pragma unroll
    for (int i = 0; i < 4; i++) {
        int r = r0 + 16 * i;
        kv[i] = *(const float4*)&kbase[(size_t)r * Dc + c4 * 4];
        vv[i] = *(const float4*)&vbase[(size_t)r * Dc + c4 * 4];
    }
#pragma unroll
    for (int i = 0; i < 4; i++) {
        int r = r0 + 16 * i;
        uint32_t* pk = &Ks[r * 68 + c4 * 4];
        pk[0] = f2tf(kv[i].x); pk[1] = f2tf(kv[i].y); pk[2] = f2tf(kv[i].z); pk[3] = f2tf(kv[i].w);
        uint32_t* pv = &Vs[r * 72 + c4 * 4];
        pv[0] = f2tf(vv[i].x); pv[1] = f2tf(vv[i].y); pv[2] = f2tf(vv[i].z); pv[3] = f2tf(vv[i].w);
    }

    float m0r = -INFINITY, m1r = -INFINITY;  // running max, rows wq+g / wq+g+8
    float l0r = 0.0f, l1r = 0.0f;            // running sum (replicated per quad)
    float acc[8][4] = {};                    // ctx accum [nf][frag]

    for (int s = 0; s < 32; s++) {
        __syncthreads();   // staged K/V visible

        // Prefetch next K (V after score phase)
        if (s + 1 < 32) {
            const int kk = (s + 1) << 6;
#pragma unroll
            for (int i = 0; i < 4; i++)
                kv[i] = *(const float4*)&kbase[(size_t)(kk + r0 + 16 * i) * Dc + c4 * 4];
        }

        // ---- Score MMA: 16q x 64k per warp ----
        float c[8][4] = {};
#pragma unroll
        for (int ks = 0; ks < 8; ks++) {
            uint32_t a0 = Qs[(wq + g) * 68 + ks * 8 + t];
            uint32_t a1 = Qs[(wq + g + 8) * 68 + ks * 8 + t];
            uint32_t a2 = Qs[(wq + g) * 68 + ks * 8 + t + 4];
            uint32_t a3 = Qs[(wq + g + 8) * 68 + ks * 8 + t + 4];
#pragma unroll
            for (int nf = 0; nf < 8; nf++) {
                uint32_t b0 = Ks[(nf * 8 + g) * 68 + ks * 8 + t];
                uint32_t b1 = Ks[(nf * 8 + g) * 68 + ks * 8 + t + 4];
                mma8(c[nf], a0, a1, a2, a3, b0, b1);
            }
        }

        // Prefetch next V
        if (s + 1 < 32) {
            const int kk = (s + 1) << 6;
#pragma unroll
            for (int i = 0; i < 4; i++)
                vv[i] = *(const float4*)&vbase[(size_t)(kk + r0 + 16 * i) * Dc + c4 * 4];
        }

        // ---- Raw score STG + in-register row max ----
        float mx0 = -INFINITY, mx1 = -INFINITY;
#pragma unroll
        for (int nf = 0; nf < 8; nf++) {
            int col = (s << 6) + nf * 8 + 2 * t;
            *(float2*)&attn_base[(size_t)(wq + g) * Sc + col] =
                make_float2(c[nf][0], c[nf][1]);
            *(float2*)&attn_base[(size_t)(wq + g + 8) * Sc + col] =
                make_float2(c[nf][2], c[nf][3]);
            mx0 = fmaxf(mx0, fmaxf(c[nf][0], c[nf][1]));
            mx1 = fmaxf(mx1, fmaxf(c[nf][2], c[nf][3]));
        }
#pragma unroll
        for (int d = 1; d < 4; d <<= 1) {
            mx0 = fmaxf(mx0, __shfl_xor_sync(0xffffffffu, mx0, d));
            mx1 = fmaxf(mx1, __shfl_xor_sync(0xffffffffu, mx1, d));
        }
        const float mn0 = fmaxf(m0r, mx0), mn1 = fmaxf(m1r, mx1);
        const float f0 = __expf(m0r - mn0), f1 = __expf(m1r - mn1);
        m0r = mn0; m1r = mn1;

        // ---- exp in regs, P store (warp-private), l update ----
        float s0 = 0.0f, s1 = 0.0f;
#pragma unroll
        for (int nf = 0; nf < 8; nf++) {
            float p0 = __expf(c[nf][0] - mn0);
            float p1 = __expf(c[nf][1] - mn0);
            float p2 = __expf(c[nf][2] - mn1);
            float p3 = __expf(c[nf][3] - mn1);
            s0 += p0 + p1; s1 += p2 + p3;
            uint2 w0 = {f2tf(p0), f2tf(p1)};
            *(uint2*)&Pw[g * 68 + nf * 8 + 2 * t] = w0;
            uint2 w1 = {f2tf(p2), f2tf(p3)};
            *(uint2*)&Pw[(g + 8) * 68 + nf * 8 + 2 * t] = w1;
        }
#pragma unroll
        for (int d = 1; d < 4; d <<= 1) {
            s0 += __shfl_xor_sync(0xffffffffu, s0, d);
            s1 += __shfl_xor_sync(0xffffffffu, s1, d);
        }
        l0r = l0r * f0 + s0;
        l1r = l1r * f1 + s1;
        __syncwarp();   // P tile write -> read (same warp only)

        // ---- Rescale acc + PV MMA: 16q x 64d over k=64 ----
#pragma unroll
        for (int nf = 0; nf < 8; nf++) {
            acc[nf][0] *= f0; acc[nf][1] *= f0;
            acc[nf][2] *= f1; acc[nf][3] *= f1;
        }
#pragma unroll
        for (int ks = 0; ks < 8; ks++) {
            const int kb = ks * 8;
            uint32_t a0 = Pw[g * 68 + kb + t];
            uint32_t a1 = Pw[(g + 8) * 68 + kb + t];
            uint32_t a2 = Pw[g * 68 + kb + t + 4];
            uint32_t a3 = Pw[(g + 8) * 68 + kb + t + 4];
#pragma unroll
            for (int nf = 0; nf < 8; nf++) {
                uint32_t b0 = Vs[(kb + t) * 72 + nf * 8 + g];
                uint32_t b1 = Vs[(kb + t + 4) * 72 + nf * 8 + g];
                mma8(acc[nf], a0, a1, a2, a3, b0, b1);
            }
        }
        __syncthreads();   // all K/V reads of this slab done

        // Stage prefetched next slab
        if (s + 1 < 32) {
#pragma unroll
            for (int i = 0; i < 4; i++) {
                int r = r0 + 16 * i;
                uint32_t* pk = &Ks[r * 68 + c4 * 4];
                pk[0] = f2tf(kv[i].x); pk[1] = f2tf(kv[i].y);
                pk[2] = f2tf(kv[i].z); pk[3] = f2tf(kv[i].w);
                uint32_t* pv = &Vs[r * 72 + c4 * 4];
                pv[0] = f2tf(vv[i].x); pv[1] = f2tf(vv[i].y);
                pv[2] = f2tf(vv[i].z); pv[3] = f2tf(vv[i].w);
            }
        }
    }

    // Per-row (m,l) for the normalize kernel (one writer per row: t==0)
    if (t == 0) {
        g_mbuf[row_g + wq + g] = m0r;
        g_lbuf[row_g + wq + g] = l0r;
        g_mbuf[row_g + wq + g + 8] = m1r;
        g_lbuf[row_g + wq + g + 8] = l1r;
    }

    // Context epilogue: out = acc / l
    const float il0 = 1.0f / l0r, il1 = 1.0f / l1r;
#pragma unroll
    for (int nf = 0; nf < 8; nf++) {
        int col = nf * 8 + 2 * t;
        *(float2*)&g_ctx[((size_t)b * Sc + q0 + wq + g) * Dc + h * HDc + col] =
            make_float2(acc[nf][0] * il0, acc[nf][1] * il0);
        *(float2*)&g_ctx[((size_t)b * Sc + q0 + wq + g + 8) * Dc + h * HDc + col] =
            make_float2(acc[nf][2] * il1, acc[nf][3] * il1);
    }
}

// ---------------------------------------------------------------------------
// Streaming normalize: attn[i] = exp(raw - m_row) / l_row  (in place)
// ---------------------------------------------------------------------------
__global__ __launch_bounds__(256) void normalize_attn(float* __restrict__ attn) {
    size_t i4 = (size_t)blockIdx.x * 256 + threadIdx.x;  // float4 index
    int row = (int)(i4 >> 9);                            // 512 float4 per row
    float mm = g_mbuf[row];
    float il = 1.0f / g_lbuf[row];
    float4 v = *((const float4*)attn + i4);
    v.x = __expf(v.x - mm) * il;
    v.y = __expf(v.y - mm) * il;
    v.z = __expf(v.z - mm) * il;
    v.w = __expf(v.w - mm) * il;
    *((float4*)attn + i4) = v;
}

// ---------------------------------------------------------------------------
extern "C" void kernel_launch(void* const* d_in, const int* in_sizes, int n_in,
                              void* d_out, int out_size) {
    const float* query = (const float*)d_in[0];
    const float* key_  = (const float*)d_in[1];
    const float* value = (const float*)d_in[2];
    const float* Wq = (const float*)d_in[3];
    const float* bq = (const float*)d_in[4];
    const float* Wk = (const float*)d_in[5];
    const float* bk = (const float*)d_in[6];
    const float* Wv = (const float*)d_in[7];
    const float* bv = (const float*)d_in[8];
    const float* Wo = (const float*)d_in[9];
    const float* bo = (const float*)d_in[10];
    float* out = (float*)d_out;

    float *dq, *dk, *dv, *dctx;
    cudaGetSymbolAddress((void**)&dq,  g_q);
    cudaGetSymbolAddress((void**)&dk,  g_k);
    cudaGetSymbolAddress((void**)&dv,  g_v);
    cudaGetSymbolAddress((void**)&dctx, g_ctx);

    const size_t OUT_ELEMS  = (size_t)Bc * Sc * Dc;           // 4,194,304
    const size_t ATTN_ELEMS = (size_t)Bc * Hc * Sc * Sc;      // 134,217,728
    float* attn_ptr;
    if ((size_t)out_size >= OUT_ELEMS + ATTN_ELEMS) {
        attn_ptr = out + OUT_ELEMS;
    } else {
        cudaGetSymbolAddress((void**)&attn_ptr, g_attn_scratch);
    }

    cudaFuncSetAttribute(attn_flash,
                         cudaFuncAttributeMaxDynamicSharedMemorySize,
                         ATTN_SMEM_BYTES);

    dim3 ggrid(BSc / 128, Dc / 128);  // 32 x 8

    gemm_bias_tc<<<ggrid, 256>>>(query, Wq, bq, dq, BSc, Dc, Dc);
    gemm_bias_tc<<<ggrid, 256>>>(key_,  Wk, bk, dk, BSc, Dc, Dc);
    gemm_bias_tc<<<ggrid, 256>>>(value, Wv, bv, dv, BSc, Dc, Dc);

    attn_flash<<<dim3(Sc / 128, Hc, Bc), 256, ATTN_SMEM_BYTES>>>(attn_ptr);

    // Normalize attn probabilities (raw -> softmax), pure streaming
    normalize_attn<<<(unsigned)(ATTN_ELEMS / 4 / 256), 256>>>(attn_ptr);

    gemm_bias_tc<<<ggrid, 256>>>(dctx, Wo, bo, out, BSc, Dc, Dc);
}

// round 12
// speedup vs baseline: 2.8195x; 1.2071x over previous
#include <cuda_runtime.h>
#include <math.h>
#include <stdint.h>

// Problem constants
#define Bc  2
#define Sc  2048
#define Dc  1024
#define Hc  16
#define HDc 64
#define BSc (Bc * Sc)
#define BHS (Bc * Hc * Sc)   // 65536 attention rows

// Scratch (device globals; allocation inside kernel_launch is forbidden)
__device__ float g_q[(size_t)Bc * Sc * Dc];
__device__ float g_k[(size_t)Bc * Sc * Dc];
__device__ float g_v[(size_t)Bc * Sc * Dc];
__device__ float g_ctx[(size_t)Bc * Sc * Dc];
__device__ float g_mbuf[BHS];
__device__ float g_lbuf[BHS];
__device__ float g_attn_scratch[(size_t)Bc * Hc * Sc * Sc];
// RN-tf32 pre-rounded operands (so cp.async + HW truncation is EXACT)
__device__ float g_inq[(size_t)BSc * Dc];
__device__ float g_ink[(size_t)BSc * Dc];
__device__ float g_inv[(size_t)BSc * Dc];
__device__ float g_wq[(size_t)Dc * Dc];
__device__ float g_wk[(size_t)Dc * Dc];
__device__ float g_wv[(size_t)Dc * Dc];
__device__ float g_wo[(size_t)Dc * Dc];

// ---------------------------------------------------------------------------
// tf32 helpers. cvt.rna rounds-to-nearest into a tf32-representable fp32
// pattern; mma operands below that pattern are truncated EXACTLY.
// ---------------------------------------------------------------------------
__device__ __forceinline__ uint32_t f2tf(float f) {
    uint32_t u;
    asm("cvt.rna.tf32.f32 %0, %1;" : "=r"(u) : "f"(f));
    return u;
}
__device__ __forceinline__ float frnd(float f) { return __uint_as_float(f2tf(f)); }
__device__ __forceinline__ uint32_t fbits(float f) { return __float_as_uint(f); }

__device__ __forceinline__ void mma8(float c[4],
                                     uint32_t a0, uint32_t a1, uint32_t a2, uint32_t a3,
                                     uint32_t b0, uint32_t b1) {
    asm volatile(
        "mma.sync.aligned.m16n8k8.row.col.f32.tf32.tf32.f32 "
        "{%0,%1,%2,%3}, {%4,%5,%6,%7}, {%8,%9}, {%0,%1,%2,%3};"
        : "+f"(c[0]), "+f"(c[1]), "+f"(c[2]), "+f"(c[3])
        : "r"(a0), "r"(a1), "r"(a2), "r"(a3), "r"(b0), "r"(b1));
}

// cp.async helpers (16B, L1-bypass)
__device__ __forceinline__ void cpa16(uint32_t s, const void* g) {
    asm volatile("cp.async.cg.shared.global [%0], [%1], 16;" :: "r"(s), "l"(g));
}
#define CPA_COMMIT() asm volatile("cp.async.commit_group;")
#define CPA_WAIT0()  asm volatile("cp.async.wait_group 0;")

// ---------------------------------------------------------------------------
// Pre-round: RN-tf32 copies of inputs and weights.
// grid.y selects tensor (0..2 inputs 4M elems, 3..6 weights 1M elems),
// grid.x*256 threads, float4 each.
// ---------------------------------------------------------------------------
__global__ __launch_bounds__(256) void pre_round(
    const float* __restrict__ q_in, const float* __restrict__ k_in,
    const float* __restrict__ v_in,
    const float* __restrict__ Wq, const float* __restrict__ Wk,
    const float* __restrict__ Wv, const float* __restrict__ Wo) {
    const float* src;
    float* dst;
    size_t n;   // float4 count
    switch (blockIdx.y) {
        case 0: src = q_in; dst = g_inq; n = (size_t)BSc * Dc / 4; break;
        case 1: src = k_in; dst = g_ink; n = (size_t)BSc * Dc / 4; break;
        case 2: src = v_in; dst = g_inv; n = (size_t)BSc * Dc / 4; break;
        case 3: src = Wq;   dst = g_wq;  n = (size_t)Dc * Dc / 4;  break;
        case 4: src = Wk;   dst = g_wk;  n = (size_t)Dc * Dc / 4;  break;
        case 5: src = Wv;   dst = g_wv;  n = (size_t)Dc * Dc / 4;  break;
        default: src = Wo;  dst = g_wo;  n = (size_t)Dc * Dc / 4;  break;
    }
    size_t i = (size_t)blockIdx.x * 256 + threadIdx.x;
    if (i >= n) return;
    float4 v = *((const float4*)src + i);
    v.x = frnd(v.x); v.y = frnd(v.y); v.z = frnd(v.z); v.w = frnd(v.w);
    *((float4*)dst + i) = v;
}

// ---------------------------------------------------------------------------
// TF32 GEMM + bias, cp.async 2-stage double buffer. Operands MUST be
// pre-rounded to tf32. C[M,N] = A[M,K] @ W[K,N] + b[N].
// CTA 128x128, BK=32, 256 thr, warp 64x32.
// ---------------------------------------------------------------------------
#define GA_W   (128 * 36)
#define GB_W   (32 * 132)
#define GST_W  (GA_W + GB_W)                  // 8832 words / stage
#define GEMM_SMEM_BYTES (2 * GST_W * 4)       // 70656 B

__device__ __forceinline__ void gemm_stage(uint32_t sA, uint32_t sB,
                                           const float* __restrict__ A,
                                           const float* __restrict__ W,
                                           int N, int K, int m0, int n0, int k0,
                                           int tid) {
#pragma unroll
    for (int i = 0; i < 4; i++) {
        int idx = tid + i * 256;
        int r = idx >> 3, c4 = idx & 7;
        cpa16(sA + (uint32_t)(r * 36 + c4 * 4) * 4,
              &A[(size_t)(m0 + r) * K + k0 + c4 * 4]);
    }
#pragma unroll
    for (int i = 0; i < 4; i++) {
        int idx = tid + i * 256;
        int r = idx >> 5, c4 = idx & 31;
        cpa16(sB + (uint32_t)(r * 132 + c4 * 4) * 4,
              &W[(size_t)(k0 + r) * N + n0 + c4 * 4]);
    }
}

__device__ __forceinline__ void gemm_body(const float* __restrict__ A,
                                          const float* __restrict__ W,
                                          const float* __restrict__ bias,
                                          float* __restrict__ C,
                                          int M, int N, int K,
                                          uint32_t* sh, bool round_out) {
    const int tid = threadIdx.x;
    const int w = tid >> 5, lane = tid & 31;
    const int g = lane >> 2, t = lane & 3;
    const int m0 = blockIdx.x * 128, n0 = blockIdx.y * 128;
    const int wm = (w & 1) * 64;
    const int wn = (w >> 1) * 32;

    const uint32_t smem_u32 = (uint32_t)__cvta_generic_to_shared(sh);

    float acc[4][4][4] = {};

    gemm_stage(smem_u32, smem_u32 + GA_W * 4, A, W, N, K, m0, n0, 0, tid);
    CPA_COMMIT();

    const int NIT = K / 32;
    for (int i = 0; i < NIT; i++) {
        CPA_WAIT0();
        __syncthreads();   // stage i visible; prior MMA reads done

        const int nb = (i + 1) & 1;
        if (i + 1 < NIT) {
            gemm_stage(smem_u32 + (uint32_t)(nb * GST_W) * 4,
                       smem_u32 + (uint32_t)(nb * GST_W + GA_W) * 4,
                       A, W, N, K, m0, n0, (i + 1) * 32, tid);
            CPA_COMMIT();
        }

        const uint32_t* As = sh + (i & 1) * GST_W;
        const uint32_t* Bs = As + GA_W;

#pragma unroll
        for (int ks = 0; ks < 4; ks++) {
            uint32_t a[4][4], bb[4][2];
#pragma unroll
            for (int mf = 0; mf < 4; mf++) {
                int r = wm + mf * 16 + g;
                a[mf][0] = As[r * 36 + ks * 8 + t];
                a[mf][2] = As[r * 36 + ks * 8 + t + 4];
                a[mf][1] = As[(r + 8) * 36 + ks * 8 + t];
                a[mf][3] = As[(r + 8) * 36 + ks * 8 + t + 4];
            }
#pragma unroll
            for (int nf = 0; nf < 4; nf++) {
                bb[nf][0] = Bs[(ks * 8 + t) * 132 + wn + nf * 8 + g];
                bb[nf][1] = Bs[(ks * 8 + t + 4) * 132 + wn + nf * 8 + g];
            }
#pragma unroll
            for (int mf = 0; mf < 4; mf++)
#pragma unroll
                for (int nf = 0; nf < 4; nf++)
                    mma8(acc[mf][nf], a[mf][0], a[mf][1], a[mf][2], a[mf][3],
                         bb[nf][0], bb[nf][1]);
        }
        __syncthreads();   // MMA reads of buffer i&1 done before re-stage
    }

#pragma unroll
    for (int mf = 0; mf < 4; mf++) {
#pragma unroll
        for (int nf = 0; nf < 4; nf++) {
            int col = n0 + wn + nf * 8 + 2 * t;
            float b0v = bias[col], b1v = bias[col + 1];
            int row = m0 + wm + mf * 16 + g;
            float2 v0 = {acc[mf][nf][0] + b0v, acc[mf][nf][1] + b1v};
            float2 v1 = {acc[mf][nf][2] + b0v, acc[mf][nf][3] + b1v};
            if (round_out) {   // downstream kernel uses these as MMA operands
                v0.x = frnd(v0.x); v0.y = frnd(v0.y);
                v1.x = frnd(v1.x); v1.y = frnd(v1.y);
            }
            *(float2*)&C[(size_t)row * N + col] = v0;
            *(float2*)&C[(size_t)(row + 8) * N + col] = v1;
        }
    }
}

// Fused QKV projection: blockIdx.z selects (input, weights, bias, output).
// Outputs are RN-rounded to tf32 (consumed by the attention MMAs).
__global__ __launch_bounds__(256) void qkv_gemm(
    const float* __restrict__ bq, const float* __restrict__ bk,
    const float* __restrict__ bv) {
    extern __shared__ uint32_t sh[];
    const float *A, *W, *bias;
    float* C;
    if (blockIdx.z == 0)      { A = g_inq; W = g_wq; bias = bq; C = g_q; }
    else if (blockIdx.z == 1) { A = g_ink; W = g_wk; bias = bk; C = g_k; }
    else                      { A = g_inv; W = g_wv; bias = bv; C = g_v; }
    gemm_body(A, W, bias, C, BSc, Dc, Dc, sh, true);
}

// Output projection: ctx (pre-rounded) @ Wo (pre-rounded) + bo -> fp32 out
__global__ __launch_bounds__(256) void out_gemm(const float* __restrict__ bo,
                                                float* __restrict__ out) {
    extern __shared__ uint32_t sh[];
    gemm_body(g_ctx, g_wo, bo, out, BSc, Dc, Dc, sh, false);
}

// ---------------------------------------------------------------------------
// Flash attention: 128-query CTA, warp-private softmax (16q x 64k per warp).
// Q/K/V are already tf32-rounded -> raw-bit staging is exact. P gets cvt.rna.
// m/l in registers; 2 syncthreads + 1 syncwarp per slab; K/V reg prefetch.
// Smem words: Qs 128*68 | Ks 64*68 | Vs 64*72 | Ps 8*1088  = 26368 (105472 B)
// ---------------------------------------------------------------------------
#define AQ    0
#define AK    8704
#define AV    13056
#define APT   17664
#define AWORDS 26368
#define ATTN_SMEM_BYTES (AWORDS * 4)

__global__ __launch_bounds__(256, 2) void attn_flash(float* __restrict__ attn) {
    extern __shared__ uint32_t sh[];
    uint32_t* Qs = sh + AQ;          // Q bits [q][d] stride 68 (pre-scaled)
    uint32_t* Ks = sh + AK;          // K bits [key][d] stride 68
    uint32_t* Vs = sh + AV;          // V bits [key][d] stride 72
    uint32_t* Ps = sh + APT;         // per-warp P bits [16][64] stride 68

    const int tid = threadIdx.x;
    const int w = tid >> 5, lane = tid & 31;
    const int g = lane >> 2, t = lane & 3;
    const int b = blockIdx.z, h = blockIdx.y, q0 = blockIdx.x << 7;
    const int wq = w * 16;

    const int row_g = (b * Hc + h) * Sc + q0;
    float* attn_base = attn + (size_t)row_g * Sc;
    const float* kbase = g_k + ((size_t)b * Sc) * Dc + h * HDc;
    const float* vbase = g_v + ((size_t)b * Sc) * Dc + h * HDc;

    const int r0 = tid >> 4, c4 = tid & 15;
    uint32_t* Pw = Ps + w * 1088;

    // Stage Q 128x64 (x 1/sqrt(64) = 0.125, exact power of two -> stays tf32)
#pragma unroll
    for (int i = 0; i < 8; i++) {
        int idx = tid + i * 256;
        int r = idx >> 4, cc = idx & 15;
        float4 v = *(const float4*)&g_q[((size_t)b * Sc + q0 + r) * Dc + h * HDc + cc * 4];
        uint32_t* p = &Qs[r * 68 + cc * 4];
        p[0] = fbits(v.x * 0.125f); p[1] = fbits(v.y * 0.125f);
        p[2] = fbits(v.z * 0.125f); p[3] = fbits(v.w * 0.125f);
    }

    // Prefetch + stage slab 0 (raw bits, already tf32)
    float4 kv[4], vv[4];
#pragma unroll
    for (int i = 0; i < 4; i++) {
        int r = r0 + 16 * i;
        kv[i] = *(const float4*)&kbase[(size_t)r * Dc + c4 * 4];
        vv[i] = *(const float4*)&vbase[(size_t)r * Dc + c4 * 4];
    }
#pragma unroll
    for (int i = 0; i < 4; i++) {
        int r = r0 + 16 * i;
        *(uint4*)&Ks[r * 68 + c4 * 4] = *(uint4*)&kv[i];
        *(uint4*)&Vs[r * 72 + c4 * 4] = *(uint4*)&vv[i];
    }

    float m0r = -INFINITY, m1r = -INFINITY;
    float l0r = 0.0f, l1r = 0.0f;
    float acc[8][4] = {};

    for (int s = 0; s < 32; s++) {
        __syncthreads();   // staged K/V visible

        if (s + 1 < 32) {
            const int kk = (s + 1) << 6;
#pragma unroll
            for (int i = 0; i < 4; i++)
                kv[i] = *(const float4*)&kbase[(size_t)(kk + r0 + 16 * i) * Dc + c4 * 4];
        }

        // ---- Score MMA: 16q x 64k per warp ----
        float c[8][4] = {};
#pragma unroll
        for (int ks = 0; ks < 8; ks++) {
            uint32_t a0 = Qs[(wq + g) * 68 + ks * 8 + t];
            uint32_t a1 = Qs[(wq + g + 8) * 68 + ks * 8 + t];
            uint32_t a2 = Qs[(wq + g) * 68 + ks * 8 + t + 4];
            uint32_t a3 = Qs[(wq + g + 8) * 68 + ks * 8 + t + 4];
#pragma unroll
            for (int nf = 0; nf < 8; nf++) {
                uint32_t b0 = Ks[(nf * 8 + g) * 68 + ks * 8 + t];
                uint32_t b1 = Ks[(nf * 8 + g) * 68 + ks * 8 + t + 4];
                mma8(c[nf], a0, a1, a2, a3, b0, b1);
            }
        }

        if (s + 1 < 32) {
            const int kk = (s + 1) << 6;
#pragma unroll
            for (int i = 0; i < 4; i++)
                vv[i] = *(const float4*)&vbase[(size_t)(kk + r0 + 16 * i) * Dc + c4 * 4];
        }

        // ---- Raw score STG + row max ----
        float mx0 = -INFINITY, mx1 = -INFINITY;
#pragma unroll
        for (int nf = 0; nf < 8; nf++) {
            int col = (s << 6) + nf * 8 + 2 * t;
            *(float2*)&attn_base[(size_t)(wq + g) * Sc + col] =
                make_float2(c[nf][0], c[nf][1]);
            *(float2*)&attn_base[(size_t)(wq + g + 8) * Sc + col] =
                make_float2(c[nf][2], c[nf][3]);
            mx0 = fmaxf(mx0, fmaxf(c[nf][0], c[nf][1]));
            mx1 = fmaxf(mx1, fmaxf(c[nf][2], c[nf][3]));
        }
#pragma unroll
        for (int d = 1; d < 4; d <<= 1) {
            mx0 = fmaxf(mx0, __shfl_xor_sync(0xffffffffu, mx0, d));
            mx1 = fmaxf(mx1, __shfl_xor_sync(0xffffffffu, mx1, d));
        }
        const float mn0 = fmaxf(m0r, mx0), mn1 = fmaxf(m1r, mx1);
        const float f0 = __expf(m0r - mn0), f1 = __expf(m1r - mn1);
        m0r = mn0; m1r = mn1;

        // ---- exp in regs, P store (cvt.rna — fp32-born operand), l update ----
        float s0 = 0.0f, s1 = 0.0f;
#pragma unroll
        for (int nf = 0; nf < 8; nf++) {
            float p0 = __expf(c[nf][0] - mn0);
            float p1 = __expf(c[nf][1] - mn0);
            float p2 = __expf(c[nf][2] - mn1);
            float p3 = __expf(c[nf][3] - mn1);
            s0 += p0 + p1; s1 += p2 + p3;
            uint2 w0 = {f2tf(p0), f2tf(p1)};
            *(uint2*)&Pw[g * 68 + nf * 8 + 2 * t] = w0;
            uint2 w1 = {f2tf(p2), f2tf(p3)};
            *(uint2*)&Pw[(g + 8) * 68 + nf * 8 + 2 * t] = w1;
        }
#pragma unroll
        for (int d = 1; d < 4; d <<= 1) {
            s0 += __shfl_xor_sync(0xffffffffu, s0, d);
            s1 += __shfl_xor_sync(0xffffffffu, s1, d);
        }
        l0r = l0r * f0 + s0;
        l1r = l1r * f1 + s1;
        __syncwarp();

        // ---- Rescale acc + PV MMA ----
#pragma unroll
        for (int nf = 0; nf < 8; nf++) {
            acc[nf][0] *= f0; acc[nf][1] *= f0;
            acc[nf][2] *= f1; acc[nf][3] *= f1;
        }
#pragma unroll
        for (int ks = 0; ks < 8; ks++) {
            const int kb = ks * 8;
            uint32_t a0 = Pw[g * 68 + kb + t];
            uint32_t a1 = Pw[(g + 8) * 68 + kb + t];
            uint32_t a2 = Pw[g * 68 + kb + t + 4];
            uint32_t a3 = Pw[(g + 8) * 68 + kb + t + 4];
#pragma unroll
            for (int nf = 0; nf < 8; nf++) {
                uint32_t b0 = Vs[(kb + t) * 72 + nf * 8 + g];
                uint32_t b1 = Vs[(kb + t + 4) * 72 + nf * 8 + g];
                mma8(acc[nf], a0, a1, a2, a3, b0, b1);
            }
        }
        __syncthreads();

        if (s + 1 < 32) {
#pragma unroll
            for (int i = 0; i < 4; i++) {
                int r = r0 + 16 * i;
                *(uint4*)&Ks[r * 68 + c4 * 4] = *(uint4*)&kv[i];
                *(uint4*)&Vs[r * 72 + c4 * 4] = *(uint4*)&vv[i];
            }
        }
    }

    if (t == 0) {
        g_mbuf[row_g + wq + g] = m0r;
        g_lbuf[row_g + wq + g] = l0r;
        g_mbuf[row_g + wq + g + 8] = m1r;
        g_lbuf[row_g + wq + g + 8] = l1r;
    }

    // Context epilogue: out = acc / l, RN-rounded to tf32 (feeds out_gemm)
    const float il0 = 1.0f / l0r, il1 = 1.0f / l1r;
#pragma unroll
    for (int nf = 0; nf < 8; nf++) {
        int col = nf * 8 + 2 * t;
        *(float2*)&g_ctx[((size_t)b * Sc + q0 + wq + g) * Dc + h * HDc + col] =
            make_float2(frnd(acc[nf][0] * il0), frnd(acc[nf][1] * il0));
        *(float2*)&g_ctx[((size_t)b * Sc + q0 + wq + g + 8) * Dc + h * HDc + col] =
            make_float2(frnd(acc[nf][2] * il1), frnd(acc[nf][3] * il1));
    }
}

// ---------------------------------------------------------------------------
// Streaming normalize: attn[i] = exp(raw - m_row) / l_row  (in place)
// ---------------------------------------------------------------------------
__global__ __launch_bounds__(256) void normalize_attn(float* __restrict__ attn) {
    size_t i4 = (size_t)blockIdx.x * 256 + threadIdx.x;
    int row = (int)(i4 >> 9);
    float mm = g_mbuf[row];
    float il = 1.0f / g_lbuf[row];
    float4 v = *((const float4*)attn + i4);
    v.x = __expf(v.x - mm) * il;
    v.y = __expf(v.y - mm) * il;
    v.z = __expf(v.z - mm) * il;
    v.w = __expf(v.w - mm) * il;
    *((float4*)attn + i4) = v;
}

// ---------------------------------------------------------------------------
extern "C" void kernel_launch(void* const* d_in, const int* in_sizes, int n_in,
                              void* d_out, int out_size) {
    const float* query = (const float*)d_in[0];
    const float* key_  = (const float*)d_in[1];
    const float* value = (const float*)d_in[2];
    const float* bq = (const float*)d_in[4];
    const float* bk = (const float*)d_in[6];
    const float* bv = (const float*)d_in[8];
    const float* Wq = (const float*)d_in[3];
    const float* Wk = (const float*)d_in[5];
    const float* Wv = (const float*)d_in[7];
    const float* Wo = (const float*)d_in[9];
    const float* bo = (const float*)d_in[10];
    float* out = (float*)d_out;

    const size_t OUT_ELEMS  = (size_t)Bc * Sc * Dc;           // 4,194,304
    const size_t ATTN_ELEMS = (size_t)Bc * Hc * Sc * Sc;      // 134,217,728
    float* attn_ptr;
    if ((size_t)out_size >= OUT_ELEMS + ATTN_ELEMS) {
        attn_ptr = out + OUT_ELEMS;
    } else {
        cudaGetSymbolAddress((void**)&attn_ptr, g_attn_scratch);
    }

    cudaFuncSetAttribute(attn_flash,
                         cudaFuncAttributeMaxDynamicSharedMemorySize,
                         ATTN_SMEM_BYTES);
    cudaFuncSetAttribute(qkv_gemm,
                         cudaFuncAttributeMaxDynamicSharedMemorySize,
                         GEMM_SMEM_BYTES);
    cudaFuncSetAttribute(out_gemm,
                         cudaFuncAttributeMaxDynamicSharedMemorySize,
                         GEMM_SMEM_BYTES);

    // RN-round inputs + weights to tf32 (makes all cp.async truncation exact)
    pre_round<<<dim3(4096, 7), 256>>>(query, key_, value, Wq, Wk, Wv, Wo);

    // Fused Q/K/V projections (outputs RN-rounded to tf32)
    qkv_gemm<<<dim3(BSc / 128, Dc / 128, 3), 256, GEMM_SMEM_BYTES>>>(bq, bk, bv);

    attn_flash<<<dim3(Sc / 128, Hc, Bc), 256, ATTN_SMEM_BYTES>>>(attn_ptr);

    normalize_attn<<<(unsigned)(ATTN_ELEMS / 4 / 256), 256>>>(attn_ptr);

    out_gemm<<<dim3(BSc / 128, Dc / 128), 256, GEMM_SMEM_BYTES>>>(bo, out);
}